// round 4
// baseline (speedup 1.0000x reference)
#include <cuda_runtime.h>
#include <math.h>

// ---------------------------------------------------------------------------
// Problem constants
// ---------------------------------------------------------------------------
#define BB 2
#define NN 2048
#define DD 1024
#define HH 16
#define HD 64
#define MM (BB * NN)          // 4096 rows flattened
#define ELEMS (MM * DD)       // 4,194,304

// ---------------------------------------------------------------------------
// Scratch (static device globals; no allocation allowed)
// ---------------------------------------------------------------------------
__device__ float g_xn[ELEMS];
__device__ float g_t0[ELEMS];
__device__ float g_q [ELEMS];
__device__ float g_k [ELEMS];
__device__ float g_v [ELEMS];
__device__ float g_ao[ELEMS];
__device__ float g_h  [BB * DD];
__device__ float g_ada[BB * 2 * DD];

// ---------------------------------------------------------------------------
// adaLN: h = silu(emb) @ Wada1            (grid (4,2), 256 thr)
// ---------------------------------------------------------------------------
__global__ void ada_fc1(const float* __restrict__ emb, const float* __restrict__ W,
                        float* __restrict__ h) {
    int b = blockIdx.y;
    int o = blockIdx.x * 256 + threadIdx.x;          // 0..1023
    __shared__ float se[DD];
    for (int i = threadIdx.x; i < DD; i += 256) {
        float e = emb[b * DD + i];
        se[i] = e / (1.0f + expf(-e));
    }
    __syncthreads();
    float acc = 0.0f;
    #pragma unroll 8
    for (int i = 0; i < DD; i++) acc += se[i] * W[i * DD + o];
    h[b * DD + o] = acc;
}

// ada = h @ Wada2 + bada2                 (grid (8,2), 256 thr) -> [B, 2D]
__global__ void ada_fc2(const float* __restrict__ h, const float* __restrict__ W,
                        const float* __restrict__ bias, float* __restrict__ ada) {
    int b = blockIdx.y;
    int o = blockIdx.x * 256 + threadIdx.x;          // 0..2047
    __shared__ float sh[DD];
    for (int i = threadIdx.x; i < DD; i += 256) sh[i] = h[b * DD + i];
    __syncthreads();
    float acc = bias[o];
    #pragma unroll 8
    for (int i = 0; i < DD; i++) acc += sh[i] * W[i * (2 * DD) + o];
    ada[b * 2 * DD + o] = acc;
}

// ---------------------------------------------------------------------------
// LayerNorm (no affine) + adaLN scale/shift. One block per row.
// ---------------------------------------------------------------------------
__global__ void ln_mod(const float* __restrict__ x, const float* __restrict__ ada,
                       float* __restrict__ xn) {
    int row = blockIdx.x;             // 0..4095
    int b = row >> 11;                // row / 2048
    int tid = threadIdx.x;
    const float* xr = x + (size_t)row * DD;

    float4 xv = *(const float4*)(xr + tid * 4);
    float s  = xv.x + xv.y + xv.z + xv.w;
    float s2 = xv.x * xv.x + xv.y * xv.y + xv.z * xv.z + xv.w * xv.w;
    #pragma unroll
    for (int off = 16; off; off >>= 1) {
        s  += __shfl_xor_sync(0xffffffffu, s,  off);
        s2 += __shfl_xor_sync(0xffffffffu, s2, off);
    }
    __shared__ float rs[8], rs2[8];
    int wid = tid >> 5, lane = tid & 31;
    if (lane == 0) { rs[wid] = s; rs2[wid] = s2; }
    __syncthreads();
    float S = 0.f, S2 = 0.f;
    #pragma unroll
    for (int w = 0; w < 8; w++) { S += rs[w]; S2 += rs2[w]; }
    float mu  = S * (1.0f / DD);
    float var = S2 * (1.0f / DD) - mu * mu;
    float rinv = rsqrtf(var + 1e-6f);

    int c = tid * 4;
    float4 sc = *(const float4*)(ada + b * 2 * DD + DD + c);   // scale
    float4 shv = *(const float4*)(ada + b * 2 * DD + c);       // shift
    float4 o;
    o.x = (xv.x - mu) * rinv * (1.0f + sc.x) + shv.x;
    o.y = (xv.y - mu) * rinv * (1.0f + sc.y) + shv.y;
    o.z = (xv.z - mu) * rinv * (1.0f + sc.z) + shv.z;
    o.w = (xv.w - mu) * rinv * (1.0f + sc.w) + shv.w;
    *(float4*)(xn + (size_t)row * DD + c) = o;
}

// ---------------------------------------------------------------------------
// SGEMM: C[M=4096, N=1024] = A[4096,1024] @ B[1024,1024], fp32.
// 128x128 block tile, BK=8, 256 threads, 8x8 register tile per thread.
// EPI: C = X + gate_row * (A@B)   (gated residual fused into final GEMM)
// ---------------------------------------------------------------------------
template <bool EPI>
__global__ void sgemm128(const float* __restrict__ A, const float* __restrict__ B,
                         float* __restrict__ C,
                         const float* __restrict__ X, const float* __restrict__ gate) {
    __shared__ float As[8][128];
    __shared__ float Bs[8][128];

    const int bm = blockIdx.y * 128;
    const int bn = blockIdx.x * 128;
    const int tid = threadIdx.x;
    const int tx = tid & 15, ty = tid >> 4;

    const int arow = tid >> 1;            // 0..127
    const int acol = (tid & 1) * 4;       // 0 or 4
    const int brow = tid >> 5;            // 0..7
    const int bcol = (tid & 31) * 4;      // 0..124

    const float* Aptr = A + (size_t)(bm + arow) * DD + acol;
    const float* Bptr = B + (size_t)brow * DD + bn + bcol;

    float acc[8][8];
    #pragma unroll
    for (int i = 0; i < 8; i++)
        #pragma unroll
        for (int j = 0; j < 8; j++) acc[i][j] = 0.0f;

    for (int k0 = 0; k0 < DD; k0 += 8) {
        float4 av = *(const float4*)(Aptr + k0);
        float4 bv = *(const float4*)(Bptr + (size_t)k0 * DD);
        __syncthreads();
        As[acol + 0][arow] = av.x;
        As[acol + 1][arow] = av.y;
        As[acol + 2][arow] = av.z;
        As[acol + 3][arow] = av.w;
        *(float4*)&Bs[brow][bcol] = bv;
        __syncthreads();
        #pragma unroll
        for (int k = 0; k < 8; k++) {
            float a[8], b[8];
            *(float4*)(a + 0) = *(const float4*)&As[k][ty * 8 + 0];
            *(float4*)(a + 4) = *(const float4*)&As[k][ty * 8 + 4];
            *(float4*)(b + 0) = *(const float4*)&Bs[k][tx * 8 + 0];
            *(float4*)(b + 4) = *(const float4*)&Bs[k][tx * 8 + 4];
            #pragma unroll
            for (int i = 0; i < 8; i++)
                #pragma unroll
                for (int j = 0; j < 8; j++)
                    acc[i][j] += a[i] * b[j];
        }
    }

    #pragma unroll
    for (int i = 0; i < 8; i++) {
        int row = bm + ty * 8 + i;
        int bidx = row >> 11;
        int col = bn + tx * 8;
        #pragma unroll
        for (int j4 = 0; j4 < 8; j4 += 4) {
            float4 r;
            if (EPI) {
                float4 xv = *(const float4*)(X + (size_t)row * DD + col + j4);
                float4 gv = *(const float4*)(gate + bidx * DD + col + j4);
                r.x = xv.x + gv.x * acc[i][j4 + 0];
                r.y = xv.y + gv.y * acc[i][j4 + 1];
                r.z = xv.z + gv.z * acc[i][j4 + 2];
                r.w = xv.w + gv.w * acc[i][j4 + 3];
            } else {
                r.x = acc[i][j4 + 0];
                r.y = acc[i][j4 + 1];
                r.z = acc[i][j4 + 2];
                r.w = acc[i][j4 + 3];
            }
            *(float4*)(C + (size_t)row * DD + col + j4) = r;
        }
    }
}

// ---------------------------------------------------------------------------
// RoPE (in-place, each thread owns the (d, d+32) pair for q and k)
// ---------------------------------------------------------------------------
__global__ void rope_qk(float* __restrict__ q, float* __restrict__ k,
                        const float* __restrict__ rope) {
    int idx = blockIdx.x * 256 + threadIdx.x;        // < B*N*H*32 = 2^21
    int dh = idx & 31;
    int h  = (idx >> 5) & 15;
    int n  = (idx >> 9) & 2047;
    int b  = idx >> 20;
    int base = ((b * NN + n) * DD) + h * HD + dh;

    float a1 = rope[n * HD + dh];
    float a2 = rope[n * HD + dh + 32];
    float c1 = cosf(a1), s1 = sinf(a1);
    float c2 = cosf(a2), s2 = sinf(a2);

    float q1 = q[base], q2 = q[base + 32];
    q[base]      = q1 * c1 - q2 * s1;   // d<32:  t*cos - t[d+32]*sin
    q[base + 32] = q2 * c2 + q1 * s2;   // d>=32: t*cos + t[d-32]*sin

    float k1 = k[base], k2 = k[base + 32];
    k[base]      = k1 * c1 - k2 * s1;
    k[base + 32] = k2 * c2 + k1 * s2;
}

// ---------------------------------------------------------------------------
// Flash attention: grid (N/64, H, B), 256 threads.
// 64-row Q tile, stream K/V in 64-row tiles, online softmax.
// 4x4 register tiles for S=QK^T and O+=PV.
// ---------------------------------------------------------------------------
#define ASTR 68
#define SMEM_ATTN (4 * 64 * ASTR * 4)

__global__ void attn_kernel(const float* __restrict__ q, const float* __restrict__ k,
                            const float* __restrict__ v, float* __restrict__ o) {
    extern __shared__ float sm[];
    float* Qs = sm;
    float* Ks = Qs + 64 * ASTR;
    float* Vs = Ks + 64 * ASTR;
    float* Ps = Vs + 64 * ASTR;

    const int qt = blockIdx.x, h = blockIdx.y, b = blockIdx.z;
    const int tid = threadIdx.x;
    const int tx = tid & 15, ty = tid >> 4;
    const int hoff = h * HD;
    const size_t bbase = (size_t)b * NN * DD;

    for (int i = tid; i < 64 * 64; i += 256) {
        int r = i >> 6, c = i & 63;
        Qs[r * ASTR + c] = q[bbase + (size_t)(qt * 64 + r) * DD + hoff + c] * 0.125f;
    }

    float m_i[4], l_i[4], O[4][4];
    #pragma unroll
    for (int i = 0; i < 4; i++) {
        m_i[i] = -1e30f; l_i[i] = 0.0f;
        #pragma unroll
        for (int j = 0; j < 4; j++) O[i][j] = 0.0f;
    }

    for (int kt = 0; kt < 32; kt++) {
        __syncthreads();   // guards Qs (first iter) and Ks/Vs/Ps reads of prev iter
        for (int i = tid; i < 64 * 64; i += 256) {
            int r = i >> 6, c = i & 63;
            size_t g = bbase + (size_t)(kt * 64 + r) * DD + hoff + c;
            Ks[r * ASTR + c] = k[g];
            Vs[r * ASTR + c] = v[g];
        }
        __syncthreads();

        // S = Q * K^T (4x4 per thread)
        float S[4][4];
        #pragma unroll
        for (int i = 0; i < 4; i++)
            #pragma unroll
            for (int j = 0; j < 4; j++) S[i][j] = 0.0f;
        #pragma unroll
        for (int kk = 0; kk < 64; kk += 4) {
            float qv[4][4], kv[4][4];
            #pragma unroll
            for (int i = 0; i < 4; i++)
                *(float4*)qv[i] = *(const float4*)&Qs[(ty * 4 + i) * ASTR + kk];
            #pragma unroll
            for (int j = 0; j < 4; j++)
                *(float4*)kv[j] = *(const float4*)&Ks[(tx * 4 + j) * ASTR + kk];
            #pragma unroll
            for (int i = 0; i < 4; i++)
                #pragma unroll
                for (int j = 0; j < 4; j++)
                    S[i][j] += qv[i][0] * kv[j][0] + qv[i][1] * kv[j][1]
                             + qv[i][2] * kv[j][2] + qv[i][3] * kv[j][3];
        }

        // Online softmax: row stats reduced over the 16 threads of a row group
        #pragma unroll
        for (int i = 0; i < 4; i++) {
            float mx = fmaxf(fmaxf(S[i][0], S[i][1]), fmaxf(S[i][2], S[i][3]));
            #pragma unroll
            for (int off = 8; off; off >>= 1)
                mx = fmaxf(mx, __shfl_xor_sync(0xffffffffu, mx, off));
            float mnew = fmaxf(m_i[i], mx);
            float fac = __expf(m_i[i] - mnew);
            float rs = 0.0f;
            #pragma unroll
            for (int j = 0; j < 4; j++) {
                float p = __expf(S[i][j] - mnew);
                S[i][j] = p; rs += p;
            }
            #pragma unroll
            for (int off = 8; off; off >>= 1)
                rs += __shfl_xor_sync(0xffffffffu, rs, off);
            l_i[i] = l_i[i] * fac + rs;
            m_i[i] = mnew;
            #pragma unroll
            for (int j = 0; j < 4; j++) O[i][j] *= fac;
        }

        // stage P, then O += P * V
        #pragma unroll
        for (int i = 0; i < 4; i++)
            *(float4*)&Ps[(ty * 4 + i) * ASTR + tx * 4] = *(float4*)S[i];
        __syncthreads();

        #pragma unroll
        for (int c = 0; c < 64; c += 4) {
            float pv[4][4], vv[4][4];
            #pragma unroll
            for (int i = 0; i < 4; i++)
                *(float4*)pv[i] = *(const float4*)&Ps[(ty * 4 + i) * ASTR + c];
            #pragma unroll
            for (int cc = 0; cc < 4; cc++)
                *(float4*)vv[cc] = *(const float4*)&Vs[(c + cc) * ASTR + tx * 4];
            #pragma unroll
            for (int i = 0; i < 4; i++)
                #pragma unroll
                for (int j = 0; j < 4; j++)
                    O[i][j] += pv[i][0] * vv[0][j] + pv[i][1] * vv[1][j]
                             + pv[i][2] * vv[2][j] + pv[i][3] * vv[3][j];
        }
    }

    #pragma unroll
    for (int i = 0; i < 4; i++) {
        float inv = 1.0f / l_i[i];
        float4 r;
        r.x = O[i][0] * inv; r.y = O[i][1] * inv;
        r.z = O[i][2] * inv; r.w = O[i][3] * inv;
        *(float4*)&o[bbase + (size_t)(qt * 64 + ty * 4 + i) * DD + hoff + tx * 4] = r;
    }
}

// ---------------------------------------------------------------------------
// Launcher
// ---------------------------------------------------------------------------
extern "C" void kernel_launch(void* const* d_in, const int* in_sizes, int n_in,
                              void* d_out, int out_size) {
    const float* x     = (const float*)d_in[0];
    const float* emb   = (const float*)d_in[1];
    const float* gate  = (const float*)d_in[2];
    // d_in[3] = crossattn_emb: unused by the reference
    const float* rope  = (const float*)d_in[4];
    const float* Wq1   = (const float*)d_in[5];
    const float* Wq2   = (const float*)d_in[6];
    const float* Wk1   = (const float*)d_in[7];
    const float* Wk2   = (const float*)d_in[8];
    const float* Wv    = (const float*)d_in[9];
    const float* Wo    = (const float*)d_in[10];
    const float* Wada1 = (const float*)d_in[11];
    const float* Wada2 = (const float*)d_in[12];
    const float* bada2 = (const float*)d_in[13];
    float* out = (float*)d_out;

    float *xn_p, *t0_p, *q_p, *k_p, *v_p, *ao_p, *h_p, *ada_p;
    cudaGetSymbolAddress((void**)&xn_p,  g_xn);
    cudaGetSymbolAddress((void**)&t0_p,  g_t0);
    cudaGetSymbolAddress((void**)&q_p,   g_q);
    cudaGetSymbolAddress((void**)&k_p,   g_k);
    cudaGetSymbolAddress((void**)&v_p,   g_v);
    cudaGetSymbolAddress((void**)&ao_p,  g_ao);
    cudaGetSymbolAddress((void**)&h_p,   g_h);
    cudaGetSymbolAddress((void**)&ada_p, g_ada);

    cudaFuncSetAttribute(attn_kernel,
                         cudaFuncAttributeMaxDynamicSharedMemorySize, SMEM_ATTN);

    // adaLN modulation
    ada_fc1<<<dim3(4, 2), 256>>>(emb, Wada1, h_p);
    ada_fc2<<<dim3(8, 2), 256>>>(h_p, Wada2, bada2, ada_p);

    // LayerNorm + scale/shift
    ln_mod<<<MM, 256>>>(x, ada_p, xn_p);

    // Projections
    dim3 gg(DD / 128, MM / 128);   // (8, 32)
    sgemm128<false><<<gg, 256>>>(xn_p, Wq1, t0_p, nullptr, nullptr);
    sgemm128<false><<<gg, 256>>>(t0_p, Wq2, q_p,  nullptr, nullptr);
    sgemm128<false><<<gg, 256>>>(xn_p, Wk1, t0_p, nullptr, nullptr);
    sgemm128<false><<<gg, 256>>>(t0_p, Wk2, k_p,  nullptr, nullptr);
    sgemm128<false><<<gg, 256>>>(xn_p, Wv,  v_p,  nullptr, nullptr);

    // RoPE on q and k (in place)
    rope_qk<<<(BB * NN * HH * 32) / 256, 256>>>(q_p, k_p, rope);

    // Attention
    attn_kernel<<<dim3(NN / 64, HH, BB), 256, SMEM_ATTN>>>(q_p, k_p, v_p, ao_p);

    // Output projection + gated residual (fused)
    sgemm128<true><<<gg, 256>>>(ao_p, Wo, out, x, gate);
}

// round 6
// speedup vs baseline: 5.4829x; 5.4829x over previous
#include <cuda_runtime.h>
#include <math.h>

// ---------------------------------------------------------------------------
// Problem constants
// ---------------------------------------------------------------------------
#define BB 2
#define NN 2048
#define DD 1024
#define HH 16
#define HD 64
#define MM (BB * NN)          // 4096 rows flattened
#define ELEMS (MM * DD)       // 4,194,304

// ---------------------------------------------------------------------------
// Scratch (static device globals; no allocation allowed)
// ---------------------------------------------------------------------------
__device__ float g_xn[ELEMS];
__device__ float g_t0[ELEMS];
__device__ float g_q [ELEMS];
__device__ float g_k [ELEMS];
__device__ float g_v [ELEMS];
__device__ float g_ao[ELEMS];
__device__ float g_h  [BB * DD];
__device__ float g_ada[BB * 2 * DD];
__device__ float g_wr[6 * DD * DD];    // tf32-rounded weights

// ---------------------------------------------------------------------------
// Helpers
// ---------------------------------------------------------------------------
__device__ __forceinline__ unsigned f2tf_u(float x) {
    unsigned r;
    asm("cvt.rna.tf32.f32 %0, %1;" : "=r"(r) : "f"(x));
    return r;
}
__device__ __forceinline__ float f2tf(float x) {
    return __uint_as_float(f2tf_u(x));
}
__device__ __forceinline__ void cp16(void* s, const void* g) {
    unsigned sa = (unsigned)__cvta_generic_to_shared(s);
    asm volatile("cp.async.cg.shared.global [%0], [%1], 16;" :: "r"(sa), "l"(g));
}
#define CP_COMMIT asm volatile("cp.async.commit_group;")
#define CP_WAIT0  asm volatile("cp.async.wait_group 0;")

__device__ __forceinline__ void mma_tf32(float* c, const unsigned* a, const unsigned* b) {
    asm volatile(
        "mma.sync.aligned.m16n8k8.row.col.f32.tf32.tf32.f32 "
        "{%0,%1,%2,%3}, {%4,%5,%6,%7}, {%8,%9}, {%0,%1,%2,%3};"
        : "+f"(c[0]), "+f"(c[1]), "+f"(c[2]), "+f"(c[3])
        : "r"(a[0]), "r"(a[1]), "r"(a[2]), "r"(a[3]), "r"(b[0]), "r"(b[1]));
}

// ---------------------------------------------------------------------------
// Weight rounding: dst = round_to_tf32(src)
// ---------------------------------------------------------------------------
__global__ void round_w(const float* __restrict__ src, float* __restrict__ dst) {
    int i = blockIdx.x * 256 + threadIdx.x;
    float4 v = *(const float4*)(src + i * 4);
    float4 o;
    o.x = f2tf(v.x); o.y = f2tf(v.y); o.z = f2tf(v.z); o.w = f2tf(v.w);
    *(float4*)(dst + i * 4) = o;
}

// ---------------------------------------------------------------------------
// adaLN: h = silu(emb) @ Wada1 ; ada = h @ Wada2 + b   (small fp32 kernels)
// ---------------------------------------------------------------------------
__global__ void ada_fc1(const float* __restrict__ emb, const float* __restrict__ W,
                        float* __restrict__ h) {
    int b = blockIdx.y;
    int o = blockIdx.x * 256 + threadIdx.x;
    __shared__ float se[DD];
    for (int i = threadIdx.x; i < DD; i += 256) {
        float e = emb[b * DD + i];
        se[i] = e / (1.0f + expf(-e));
    }
    __syncthreads();
    float acc = 0.0f;
    #pragma unroll 8
    for (int i = 0; i < DD; i++) acc += se[i] * W[i * DD + o];
    h[b * DD + o] = acc;
}

__global__ void ada_fc2(const float* __restrict__ h, const float* __restrict__ W,
                        const float* __restrict__ bias, float* __restrict__ ada) {
    int b = blockIdx.y;
    int o = blockIdx.x * 256 + threadIdx.x;
    __shared__ float sh[DD];
    for (int i = threadIdx.x; i < DD; i += 256) sh[i] = h[b * DD + i];
    __syncthreads();
    float acc = bias[o];
    #pragma unroll 8
    for (int i = 0; i < DD; i++) acc += sh[i] * W[i * (2 * DD) + o];
    ada[b * 2 * DD + o] = acc;
}

// ---------------------------------------------------------------------------
// LayerNorm + adaLN scale/shift (output rounded to tf32: feeds GEMMs)
// ---------------------------------------------------------------------------
__global__ void ln_mod(const float* __restrict__ x, const float* __restrict__ ada,
                       float* __restrict__ xn) {
    int row = blockIdx.x;
    int b = row >> 11;
    int tid = threadIdx.x;
    const float* xr = x + (size_t)row * DD;

    float4 xv = *(const float4*)(xr + tid * 4);
    float s  = xv.x + xv.y + xv.z + xv.w;
    float s2 = xv.x * xv.x + xv.y * xv.y + xv.z * xv.z + xv.w * xv.w;
    #pragma unroll
    for (int off = 16; off; off >>= 1) {
        s  += __shfl_xor_sync(0xffffffffu, s,  off);
        s2 += __shfl_xor_sync(0xffffffffu, s2, off);
    }
    __shared__ float rs[8], rs2[8];
    int wid = tid >> 5, lane = tid & 31;
    if (lane == 0) { rs[wid] = s; rs2[wid] = s2; }
    __syncthreads();
    float S = 0.f, S2 = 0.f;
    #pragma unroll
    for (int w = 0; w < 8; w++) { S += rs[w]; S2 += rs2[w]; }
    float mu  = S * (1.0f / DD);
    float var = S2 * (1.0f / DD) - mu * mu;
    float rinv = rsqrtf(var + 1e-6f);

    int c = tid * 4;
    float4 sc = *(const float4*)(ada + b * 2 * DD + DD + c);
    float4 shv = *(const float4*)(ada + b * 2 * DD + c);
    float4 o;
    o.x = f2tf((xv.x - mu) * rinv * (1.0f + sc.x) + shv.x);
    o.y = f2tf((xv.y - mu) * rinv * (1.0f + sc.y) + shv.y);
    o.z = f2tf((xv.z - mu) * rinv * (1.0f + sc.z) + shv.z);
    o.w = f2tf((xv.w - mu) * rinv * (1.0f + sc.w) + shv.w);
    *(float4*)(xn + (size_t)row * DD + c) = o;
}

// ---------------------------------------------------------------------------
// tf32 tensor-core GEMM: C[4096,1024] = A @ B
// 128x128x16 block tile, 8 warps (2x4), warp tile 64x32, m16n8k8 mma,
// cp.async double-buffered. MODE 0: C = tf32_round(A@B). MODE 1: fused
// gated-residual epilogue C = X + gate*(A@B) in fp32.
// ---------------------------------------------------------------------------
#define ASTRIDE 20     // 16 + 4 pad (floats)
#define BSTRIDE 132    // 128 + 4 pad

template <int MODE>
__global__ void tgemm(const float* __restrict__ A, const float* __restrict__ B,
                      float* __restrict__ C,
                      const float* __restrict__ X, const float* __restrict__ gate) {
    __shared__ float As[2][128 * ASTRIDE];
    __shared__ float Bs[2][16 * BSTRIDE];

    const int bm = blockIdx.y * 128;
    const int bn = blockIdx.x * 128;
    const int tid = threadIdx.x;
    const int warp = tid >> 5, lane = tid & 31;
    const int gid = lane >> 2, tig = lane & 3;
    const int wm = (warp >> 2) * 64;   // 0 or 64
    const int wn = (warp & 3) * 32;    // 0..96

    float acc[4][4][4];
    #pragma unroll
    for (int mi = 0; mi < 4; mi++)
        #pragma unroll
        for (int ni = 0; ni < 4; ni++)
            #pragma unroll
            for (int r = 0; r < 4; r++) acc[mi][ni][r] = 0.0f;

    // load issue helper (2 chunks per thread per tensor)
    auto issue = [&](int st, int k0) {
        #pragma unroll
        for (int i = 0; i < 2; i++) {
            int c = tid + i * 256;
            int ar = c >> 2, ak = c & 3;
            cp16(&As[st][ar * ASTRIDE + ak * 4],
                 &A[(size_t)(bm + ar) * DD + k0 + ak * 4]);
            int br = c >> 5, bc = c & 31;
            cp16(&Bs[st][br * BSTRIDE + bc * 4],
                 &B[(size_t)(k0 + br) * DD + bn + bc * 4]);
        }
    };

    issue(0, 0);
    CP_COMMIT;

    int cur = 0;
    for (int kt = 0; kt < DD / 16; kt++) {
        CP_WAIT0;
        __syncthreads();
        if (kt + 1 < DD / 16) {
            issue(cur ^ 1, (kt + 1) * 16);
            CP_COMMIT;
        }
        const float* as = As[cur];
        const float* bs = Bs[cur];
        #pragma unroll
        for (int kk = 0; kk < 2; kk++) {
            unsigned af[4][4], bf[4][2];
            #pragma unroll
            for (int mi = 0; mi < 4; mi++) {
                int m = wm + mi * 16;
                int k = kk * 8 + tig;
                af[mi][0] = __float_as_uint(as[(m + gid) * ASTRIDE + k]);
                af[mi][1] = __float_as_uint(as[(m + gid + 8) * ASTRIDE + k]);
                af[mi][2] = __float_as_uint(as[(m + gid) * ASTRIDE + k + 4]);
                af[mi][3] = __float_as_uint(as[(m + gid + 8) * ASTRIDE + k + 4]);
            }
            #pragma unroll
            for (int ni = 0; ni < 4; ni++) {
                int n = wn + ni * 8 + gid;
                bf[ni][0] = __float_as_uint(bs[(kk * 8 + tig) * BSTRIDE + n]);
                bf[ni][1] = __float_as_uint(bs[(kk * 8 + tig + 4) * BSTRIDE + n]);
            }
            #pragma unroll
            for (int mi = 0; mi < 4; mi++)
                #pragma unroll
                for (int ni = 0; ni < 4; ni++)
                    mma_tf32(acc[mi][ni], af[mi], bf[ni]);
        }
        cur ^= 1;
    }

    // epilogue
    #pragma unroll
    for (int mi = 0; mi < 4; mi++) {
        #pragma unroll
        for (int ni = 0; ni < 4; ni++) {
            int col = bn + wn + ni * 8 + 2 * tig;
            #pragma unroll
            for (int half = 0; half < 2; half++) {
                int row = bm + wm + mi * 16 + gid + half * 8;
                float v0 = acc[mi][ni][half * 2 + 0];
                float v1 = acc[mi][ni][half * 2 + 1];
                float2 r;
                if (MODE == 1) {
                    int bidx = row >> 11;
                    float2 xv = *(const float2*)(X + (size_t)row * DD + col);
                    float2 gv = *(const float2*)(gate + bidx * DD + col);
                    r.x = xv.x + gv.x * v0;
                    r.y = xv.y + gv.y * v1;
                } else {
                    r.x = f2tf(v0);
                    r.y = f2tf(v1);
                }
                *(float2*)(C + (size_t)row * DD + col) = r;
            }
        }
    }
}

// ---------------------------------------------------------------------------
// RoPE (in-place, outputs rounded to tf32 for attention mma)
// ---------------------------------------------------------------------------
__global__ void rope_qk(float* __restrict__ q, float* __restrict__ k,
                        const float* __restrict__ rope) {
    int idx = blockIdx.x * 256 + threadIdx.x;
    int dh = idx & 31;
    int h  = (idx >> 5) & 15;
    int n  = (idx >> 9) & 2047;
    int b  = idx >> 20;
    int base = ((b * NN + n) * DD) + h * HD + dh;

    float a1 = rope[n * HD + dh];
    float a2 = rope[n * HD + dh + 32];
    float c1 = cosf(a1), s1 = sinf(a1);
    float c2 = cosf(a2), s2 = sinf(a2);

    float q1 = q[base], q2 = q[base + 32];
    q[base]      = f2tf(q1 * c1 - q2 * s1);
    q[base + 32] = f2tf(q2 * c2 + q1 * s2);

    float k1 = k[base], k2 = k[base + 32];
    k[base]      = f2tf(k1 * c1 - k2 * s1);
    k[base + 32] = f2tf(k2 * c2 + k1 * s2);
}

// ---------------------------------------------------------------------------
// Flash attention with tf32 mma. grid (N/64, H, B), 128 threads (4 warps).
// Each warp owns 16 Q rows. S = Q K^T and O += P V via m16n8k8 mma.
// P staged through smem (with tf32 rounding) to form A-fragments.
// ---------------------------------------------------------------------------
#define KSTR 68
#define SMEM_ATTN (3 * 64 * KSTR * 4)   // PQs, Ks, Vs

__global__ void attn_kernel(const float* __restrict__ q, const float* __restrict__ k,
                            const float* __restrict__ v, float* __restrict__ o) {
    extern __shared__ float sm[];
    float* PQs = sm;                 // Q staging, then P per-warp slabs
    float* Ks  = PQs + 64 * KSTR;
    float* Vs  = Ks  + 64 * KSTR;

    const int qt = blockIdx.x, h = blockIdx.y, b = blockIdx.z;
    const int tid = threadIdx.x;
    const int warp = tid >> 5, lane = tid & 31;
    const int gid = lane >> 2, tig = lane & 3;
    const int hoff = h * HD;
    const size_t bbase = (size_t)b * NN * DD;

    // Stage Q (pre-scaled by HD^-0.5 = 1/8: exact power of two, stays tf32)
    for (int i = tid; i < 64 * 64; i += 128) {
        int r = i >> 6, c = i & 63;
        PQs[r * KSTR + c] = q[bbase + (size_t)(qt * 64 + r) * DD + hoff + c] * 0.125f;
    }
    __syncthreads();

    // Q A-fragments resident in registers (warp slab rows warp*16..+15)
    unsigned qa[8][4];
    {
        int m = warp * 16;
        #pragma unroll
        for (int kk = 0; kk < 8; kk++) {
            int kc = kk * 8 + tig;
            qa[kk][0] = __float_as_uint(PQs[(m + gid) * KSTR + kc]);
            qa[kk][1] = __float_as_uint(PQs[(m + gid + 8) * KSTR + kc]);
            qa[kk][2] = __float_as_uint(PQs[(m + gid) * KSTR + kc + 4]);
            qa[kk][3] = __float_as_uint(PQs[(m + gid + 8) * KSTR + kc + 4]);
        }
    }
    // From here each warp only touches its own PQs slab (P staging): no
    // cross-warp hazard on PQs.

    float m_i[2] = {-1e30f, -1e30f};
    float l_i[2] = {0.0f, 0.0f};
    float O[8][4];
    #pragma unroll
    for (int ni = 0; ni < 8; ni++)
        #pragma unroll
        for (int r = 0; r < 4; r++) O[ni][r] = 0.0f;

    for (int kt = 0; kt < NN / 64; kt++) {
        __syncthreads();      // everyone done reading Ks/Vs from prev iter
        // async load K and V tiles (64 x 64 each); 8 chunks/thread/tensor
        #pragma unroll
        for (int i = 0; i < 8; i++) {
            int c = tid + i * 128;
            int r = c >> 4, c4 = c & 15;
            size_t g = bbase + (size_t)(kt * 64 + r) * DD + hoff + c4 * 4;
            cp16(&Ks[r * KSTR + c4 * 4], &k[g]);
            cp16(&Vs[r * KSTR + c4 * 4], &v[g]);
        }
        CP_COMMIT;
        CP_WAIT0;
        __syncthreads();

        // ---- S = Q K^T ----
        float S[8][4];
        #pragma unroll
        for (int ni = 0; ni < 8; ni++)
            #pragma unroll
            for (int r = 0; r < 4; r++) S[ni][r] = 0.0f;
        #pragma unroll
        for (int kk = 0; kk < 8; kk++) {
            #pragma unroll
            for (int ni = 0; ni < 8; ni++) {
                unsigned bf[2];
                int jrow = ni * 8 + gid;
                bf[0] = __float_as_uint(Ks[jrow * KSTR + kk * 8 + tig]);
                bf[1] = __float_as_uint(Ks[jrow * KSTR + kk * 8 + tig + 4]);
                mma_tf32(S[ni], qa[kk], bf);
            }
        }

        // ---- online softmax (rows gid and gid+8 of warp slab) ----
        #pragma unroll
        for (int half = 0; half < 2; half++) {
            float mx = -1e30f;
            #pragma unroll
            for (int ni = 0; ni < 8; ni++)
                mx = fmaxf(mx, fmaxf(S[ni][half * 2], S[ni][half * 2 + 1]));
            mx = fmaxf(mx, __shfl_xor_sync(0xffffffffu, mx, 1));
            mx = fmaxf(mx, __shfl_xor_sync(0xffffffffu, mx, 2));
            float mnew = fmaxf(m_i[half], mx);
            float fac = __expf(m_i[half] - mnew);
            float rs = 0.0f;
            #pragma unroll
            for (int ni = 0; ni < 8; ni++) {
                float p0 = __expf(S[ni][half * 2]     - mnew);
                float p1 = __expf(S[ni][half * 2 + 1] - mnew);
                S[ni][half * 2]     = p0;
                S[ni][half * 2 + 1] = p1;
                rs += p0 + p1;
            }
            rs += __shfl_xor_sync(0xffffffffu, rs, 1);
            rs += __shfl_xor_sync(0xffffffffu, rs, 2);
            l_i[half] = l_i[half] * fac + rs;
            m_i[half] = mnew;
            #pragma unroll
            for (int ni = 0; ni < 8; ni++) {
                O[ni][half * 2]     *= fac;
                O[ni][half * 2 + 1] *= fac;
            }
        }

        // ---- stage P (rounded) into warp slab, reload as A-fragments ----
        {
            float* Ps = PQs + warp * 16 * KSTR;
            #pragma unroll
            for (int ni = 0; ni < 8; ni++) {
                int col = ni * 8 + 2 * tig;
                float2 p0, p1;
                p0.x = f2tf(S[ni][0]); p0.y = f2tf(S[ni][1]);
                p1.x = f2tf(S[ni][2]); p1.y = f2tf(S[ni][3]);
                *(float2*)&Ps[gid * KSTR + col]       = p0;
                *(float2*)&Ps[(gid + 8) * KSTR + col] = p1;
            }
            __syncwarp();

            // ---- O += P V ----
            #pragma unroll
            for (int kk = 0; kk < 8; kk++) {
                unsigned pa[4];
                int kc = kk * 8 + tig;
                pa[0] = __float_as_uint(Ps[gid * KSTR + kc]);
                pa[1] = __float_as_uint(Ps[(gid + 8) * KSTR + kc]);
                pa[2] = __float_as_uint(Ps[gid * KSTR + kc + 4]);
                pa[3] = __float_as_uint(Ps[(gid + 8) * KSTR + kc + 4]);
                #pragma unroll
                for (int ni = 0; ni < 8; ni++) {
                    unsigned bf[2];
                    bf[0] = __float_as_uint(Vs[(kk * 8 + tig) * KSTR + ni * 8 + gid]);
                    bf[1] = __float_as_uint(Vs[(kk * 8 + tig + 4) * KSTR + ni * 8 + gid]);
                    mma_tf32(O[ni], pa, bf);
                }
            }
            __syncwarp();   // slab reads done before next iter's P writes
        }
    }

    // ---- epilogue: normalize, round (feeds Wo GEMM), store ----
    float inv0 = 1.0f / l_i[0], inv1 = 1.0f / l_i[1];
    #pragma unroll
    for (int ni = 0; ni < 8; ni++) {
        int col = hoff + ni * 8 + 2 * tig;
        int row0 = qt * 64 + warp * 16 + gid;
        float2 r0, r1;
        r0.x = f2tf(O[ni][0] * inv0); r0.y = f2tf(O[ni][1] * inv0);
        r1.x = f2tf(O[ni][2] * inv1); r1.y = f2tf(O[ni][3] * inv1);
        *(float2*)&o[bbase + (size_t)row0 * DD + col]       = r0;
        *(float2*)&o[bbase + (size_t)(row0 + 8) * DD + col] = r1;
    }
}

// ---------------------------------------------------------------------------
// Launcher
// ---------------------------------------------------------------------------
extern "C" void kernel_launch(void* const* d_in, const int* in_sizes, int n_in,
                              void* d_out, int out_size) {
    const float* x     = (const float*)d_in[0];
    const float* emb   = (const float*)d_in[1];
    const float* gate  = (const float*)d_in[2];
    // d_in[3] = crossattn_emb: unused by the reference
    const float* rope  = (const float*)d_in[4];
    const float* Wq1   = (const float*)d_in[5];
    const float* Wq2   = (const float*)d_in[6];
    const float* Wk1   = (const float*)d_in[7];
    const float* Wk2   = (const float*)d_in[8];
    const float* Wv    = (const float*)d_in[9];
    const float* Wo    = (const float*)d_in[10];
    const float* Wada1 = (const float*)d_in[11];
    const float* Wada2 = (const float*)d_in[12];
    const float* bada2 = (const float*)d_in[13];
    float* out = (float*)d_out;

    float *xn_p, *t0_p, *q_p, *k_p, *v_p, *ao_p, *h_p, *ada_p, *wr_p;
    cudaGetSymbolAddress((void**)&xn_p,  g_xn);
    cudaGetSymbolAddress((void**)&t0_p,  g_t0);
    cudaGetSymbolAddress((void**)&q_p,   g_q);
    cudaGetSymbolAddress((void**)&k_p,   g_k);
    cudaGetSymbolAddress((void**)&v_p,   g_v);
    cudaGetSymbolAddress((void**)&ao_p,  g_ao);
    cudaGetSymbolAddress((void**)&h_p,   g_h);
    cudaGetSymbolAddress((void**)&ada_p, g_ada);
    cudaGetSymbolAddress((void**)&wr_p,  g_wr);

    cudaFuncSetAttribute(attn_kernel,
                         cudaFuncAttributeMaxDynamicSharedMemorySize, SMEM_ATTN);

    const int WSZ = DD * DD;
    float* rWq1 = wr_p + 0 * WSZ;
    float* rWq2 = wr_p + 1 * WSZ;
    float* rWk1 = wr_p + 2 * WSZ;
    float* rWk2 = wr_p + 3 * WSZ;
    float* rWv  = wr_p + 4 * WSZ;
    float* rWo  = wr_p + 5 * WSZ;

    // round weights to tf32 (RNA: kills truncation bias in HMMA)
    int rb = WSZ / 4 / 256;
    round_w<<<rb, 256>>>(Wq1, rWq1);
    round_w<<<rb, 256>>>(Wq2, rWq2);
    round_w<<<rb, 256>>>(Wk1, rWk1);
    round_w<<<rb, 256>>>(Wk2, rWk2);
    round_w<<<rb, 256>>>(Wv,  rWv);
    round_w<<<rb, 256>>>(Wo,  rWo);

    // adaLN modulation
    ada_fc1<<<dim3(4, 2), 256>>>(emb, Wada1, h_p);
    ada_fc2<<<dim3(8, 2), 256>>>(h_p, Wada2, bada2, ada_p);

    // LayerNorm + scale/shift (tf32-rounded output)
    ln_mod<<<MM, 256>>>(x, ada_p, xn_p);

    // Projections (tensor core tf32)
    dim3 gg(DD / 128, MM / 128);   // (8, 32)
    tgemm<0><<<gg, 256>>>(xn_p, rWq1, t0_p, nullptr, nullptr);
    tgemm<0><<<gg, 256>>>(t0_p, rWq2, q_p,  nullptr, nullptr);
    tgemm<0><<<gg, 256>>>(xn_p, rWk1, t0_p, nullptr, nullptr);
    tgemm<0><<<gg, 256>>>(t0_p, rWk2, k_p,  nullptr, nullptr);
    tgemm<0><<<gg, 256>>>(xn_p, rWv,  v_p,  nullptr, nullptr);

    // RoPE on q and k (in place, rounded)
    rope_qk<<<(BB * NN * HH * 32) / 256, 256>>>(q_p, k_p, rope);

    // Attention (tensor core tf32 flash)
    attn_kernel<<<dim3(NN / 64, HH, BB), 128, SMEM_ATTN>>>(q_p, k_p, v_p, ao_p);

    // Output projection + gated residual (fused, fp32 epilogue)
    tgemm<1><<<gg, 256>>>(ao_p, rWo, out, x, gate);
}

// round 9
// speedup vs baseline: 10.1150x; 1.8448x over previous
#include <cuda_runtime.h>
#include <cuda_bf16.h>
#include <math.h>

// ---------------------------------------------------------------------------
// Problem constants
// ---------------------------------------------------------------------------
#define BB 2
#define NN 2048
#define DD 1024
#define HH 16
#define HD 64
#define MM (BB * NN)          // 4096 rows flattened
#define ELEMS (MM * DD)

typedef __nv_bfloat16 bf16;

// ---------------------------------------------------------------------------
// Scratch (static device globals; no allocation allowed)
// ---------------------------------------------------------------------------
__device__ bf16  g_xn [ELEMS];
__device__ bf16  g_t0q[ELEMS];
__device__ bf16  g_t0k[ELEMS];
__device__ bf16  g_q  [ELEMS];
__device__ bf16  g_k  [ELEMS];
__device__ bf16  g_v  [ELEMS];
__device__ bf16  g_ao [ELEMS];
__device__ float g_h  [BB * DD];
__device__ float g_ada[BB * 2 * DD];
__device__ bf16  g_w1 [DD * 3 * DD];   // [1024][3072] = Wq1 | Wk1 | Wv
__device__ bf16  g_w2 [DD * 2 * DD];   // [1024][2048] = Wq2 | Wk2
__device__ bf16  g_wo [DD * DD];       // [1024][1024]

// ---------------------------------------------------------------------------
// PTX helpers
// ---------------------------------------------------------------------------
__device__ __forceinline__ void cp16(void* s, const void* g) {
    unsigned sa = (unsigned)__cvta_generic_to_shared(s);
    asm volatile("cp.async.cg.shared.global [%0], [%1], 16;" :: "r"(sa), "l"(g));
}
#define CP_COMMIT  asm volatile("cp.async.commit_group;")
#define CP_WAIT(n) asm volatile("cp.async.wait_group %0;" :: "n"(n))

__device__ __forceinline__ void ldsm_x4(unsigned& r0, unsigned& r1, unsigned& r2,
                                        unsigned& r3, const void* p) {
    unsigned a = (unsigned)__cvta_generic_to_shared(p);
    asm volatile("ldmatrix.sync.aligned.m8n8.x4.shared.b16 {%0,%1,%2,%3}, [%4];"
                 : "=r"(r0), "=r"(r1), "=r"(r2), "=r"(r3) : "r"(a));
}
__device__ __forceinline__ void ldsm_x4t(unsigned& r0, unsigned& r1, unsigned& r2,
                                         unsigned& r3, const void* p) {
    unsigned a = (unsigned)__cvta_generic_to_shared(p);
    asm volatile("ldmatrix.sync.aligned.m8n8.x4.trans.shared.b16 {%0,%1,%2,%3}, [%4];"
                 : "=r"(r0), "=r"(r1), "=r"(r2), "=r"(r3) : "r"(a));
}
__device__ __forceinline__ void mma_bf16(float* c, const unsigned* a,
                                         const unsigned* b) {
    asm volatile(
        "mma.sync.aligned.m16n8k16.row.col.f32.bf16.bf16.f32 "
        "{%0,%1,%2,%3}, {%4,%5,%6,%7}, {%8,%9}, {%0,%1,%2,%3};"
        : "+f"(c[0]), "+f"(c[1]), "+f"(c[2]), "+f"(c[3])
        : "r"(a[0]), "r"(a[1]), "r"(a[2]), "r"(a[3]), "r"(b[0]), "r"(b[1]));
}
__device__ __forceinline__ unsigned packbf(float a, float b) {
    __nv_bfloat162 t = __floats2bfloat162_rn(a, b);   // .x = a (low), .y = b
    return *reinterpret_cast<unsigned*>(&t);
}

// ---------------------------------------------------------------------------
// Weight pack: bf16 round into packed layout dst[r*ld + col0 + c]
// ---------------------------------------------------------------------------
__global__ void pack_w(const float* __restrict__ src, bf16* __restrict__ dst,
                       int ld, int col0) {
    int idx = blockIdx.x * 256 + threadIdx.x;      // 0..262143
    int r = idx >> 8;
    int c = (idx & 255) * 4;
    float4 v = *(const float4*)(src + r * 1024 + c);
    bf16* d = dst + (size_t)r * ld + col0 + c;
    *(__nv_bfloat162*)(d)     = __floats2bfloat162_rn(v.x, v.y);
    *(__nv_bfloat162*)(d + 2) = __floats2bfloat162_rn(v.z, v.w);
}

// ---------------------------------------------------------------------------
// adaLN (tiny, fp32)
// ---------------------------------------------------------------------------
__global__ void ada_fc1(const float* __restrict__ emb, const float* __restrict__ W,
                        float* __restrict__ h) {
    int b = blockIdx.y;
    int o = blockIdx.x * 256 + threadIdx.x;
    __shared__ float se[DD];
    for (int i = threadIdx.x; i < DD; i += 256) {
        float e = emb[b * DD + i];
        se[i] = e / (1.0f + expf(-e));
    }
    __syncthreads();
    float acc = 0.0f;
    #pragma unroll 8
    for (int i = 0; i < DD; i++) acc += se[i] * W[i * DD + o];
    h[b * DD + o] = acc;
}

__global__ void ada_fc2(const float* __restrict__ h, const float* __restrict__ W,
                        const float* __restrict__ bias, float* __restrict__ ada) {
    int b = blockIdx.y;
    int o = blockIdx.x * 256 + threadIdx.x;
    __shared__ float sh[DD];
    for (int i = threadIdx.x; i < DD; i += 256) sh[i] = h[b * DD + i];
    __syncthreads();
    float acc = bias[o];
    #pragma unroll 8
    for (int i = 0; i < DD; i++) acc += sh[i] * W[i * (2 * DD) + o];
    ada[b * 2 * DD + o] = acc;
}

// ---------------------------------------------------------------------------
// LayerNorm + adaLN scale/shift -> bf16
// ---------------------------------------------------------------------------
__global__ void ln_mod(const float* __restrict__ x, const float* __restrict__ ada,
                       bf16* __restrict__ xn) {
    int row = blockIdx.x;
    int b = row >> 11;
    int tid = threadIdx.x;
    const float* xr = x + (size_t)row * DD;

    float4 xv = *(const float4*)(xr + tid * 4);
    float s  = xv.x + xv.y + xv.z + xv.w;
    float s2 = xv.x * xv.x + xv.y * xv.y + xv.z * xv.z + xv.w * xv.w;
    #pragma unroll
    for (int off = 16; off; off >>= 1) {
        s  += __shfl_xor_sync(0xffffffffu, s,  off);
        s2 += __shfl_xor_sync(0xffffffffu, s2, off);
    }
    __shared__ float rs[8], rs2[8];
    int wid = tid >> 5, lane = tid & 31;
    if (lane == 0) { rs[wid] = s; rs2[wid] = s2; }
    __syncthreads();
    float S = 0.f, S2 = 0.f;
    #pragma unroll
    for (int w = 0; w < 8; w++) { S += rs[w]; S2 += rs2[w]; }
    float mu  = S * (1.0f / DD);
    float var = S2 * (1.0f / DD) - mu * mu;
    float rinv = rsqrtf(var + 1e-6f);

    int c = tid * 4;
    float4 sc  = *(const float4*)(ada + b * 2 * DD + DD + c);
    float4 shv = *(const float4*)(ada + b * 2 * DD + c);
    float o0 = (xv.x - mu) * rinv * (1.0f + sc.x) + shv.x;
    float o1 = (xv.y - mu) * rinv * (1.0f + sc.y) + shv.y;
    float o2 = (xv.z - mu) * rinv * (1.0f + sc.z) + shv.z;
    float o3 = (xv.w - mu) * rinv * (1.0f + sc.w) + shv.w;
    uint2 st;
    st.x = packbf(o0, o1);
    st.y = packbf(o2, o3);
    *(uint2*)(xn + (size_t)row * DD + c) = st;
}

// ---------------------------------------------------------------------------
// bf16 tensor-core GEMM: 128x128x32 block tile, 8 warps (2x4), warp 64x32,
// m16n8k16 mma, ldmatrix fragments, cp.async double buffer.
// MODE 0: C = bf16(A@B), B has 3 col segments -> C0/C1/C2 (QKV pack)
// MODE 1: dual A (seg0->Aa, seg1->Ab), 2 segments -> C0/C1 (Q2/K2 pack)
// MODE 2: Cf = X + gate * (A@B)  (fp32 gated-residual epilogue)
// ---------------------------------------------------------------------------
#define ASTR 40    // halves: 32 + 8 pad
#define BSTR 136   // halves: 128 + 8 pad

template <int MODE>
__global__ __launch_bounds__(256)
void tgemm(const bf16* __restrict__ Aa, const bf16* __restrict__ Ab,
           const bf16* __restrict__ B, int ldb,
           bf16* __restrict__ C0, bf16* __restrict__ C1, bf16* __restrict__ C2,
           float* __restrict__ Cf, const float* __restrict__ X,
           const float* __restrict__ gate) {
    __shared__ bf16 As[2][128 * ASTR];
    __shared__ bf16 Bs[2][32 * BSTR];

    const int bm = blockIdx.y * 128;
    const int bn = blockIdx.x * 128;
    const int seg = bn >> 10;
    const int coln = bn & 1023;
    const bf16* A = (MODE == 1 && seg == 1) ? Ab : Aa;

    const int tid = threadIdx.x;
    const int warp = tid >> 5, lane = tid & 31;
    const int gid = lane >> 2, tig = lane & 3;
    const int wm = (warp >> 2) * 64;
    const int wn = (warp & 3) * 32;

    float acc[4][4][4];
    #pragma unroll
    for (int mi = 0; mi < 4; mi++)
        #pragma unroll
        for (int ni = 0; ni < 4; ni++)
            #pragma unroll
            for (int r = 0; r < 4; r++) acc[mi][ni][r] = 0.0f;

    auto issue = [&](int st, int k0) {
        #pragma unroll
        for (int i = 0; i < 2; i++) {
            int idx = tid + i * 256;
            int ar = idx >> 2, ach = idx & 3;
            cp16(&As[st][ar * ASTR + ach * 8],
                 &A[(size_t)(bm + ar) * DD + k0 + ach * 8]);
            int br = idx >> 4, bch = idx & 15;
            cp16(&Bs[st][br * BSTR + bch * 8],
                 &B[(size_t)(k0 + br) * ldb + bn + bch * 8]);
        }
    };

    issue(0, 0);
    CP_COMMIT;

    int cur = 0;
    for (int kt = 0; kt < DD / 32; kt++) {
        CP_WAIT(0);
        __syncthreads();
        if (kt + 1 < DD / 32) {
            issue(cur ^ 1, (kt + 1) * 32);
            CP_COMMIT;
        }
        const bf16* as = As[cur];
        const bf16* bs = Bs[cur];
        #pragma unroll
        for (int kk = 0; kk < 2; kk++) {
            unsigned af[4][4], bfg[4][2];
            #pragma unroll
            for (int mi = 0; mi < 4; mi++) {
                int row = wm + mi * 16 + (lane & 15);
                int col = kk * 16 + 8 * (lane >> 4);
                ldsm_x4(af[mi][0], af[mi][1], af[mi][2], af[mi][3],
                        &as[row * ASTR + col]);
            }
            #pragma unroll
            for (int nj = 0; nj < 2; nj++) {
                int row = kk * 16 + (lane & 7) + 8 * ((lane >> 3) & 1);
                int col = wn + nj * 16 + 8 * (lane >> 4);
                unsigned r0, r1, r2, r3;
                ldsm_x4t(r0, r1, r2, r3, &bs[row * BSTR + col]);
                bfg[nj * 2][0] = r0; bfg[nj * 2][1] = r1;
                bfg[nj * 2 + 1][0] = r2; bfg[nj * 2 + 1][1] = r3;
            }
            #pragma unroll
            for (int mi = 0; mi < 4; mi++)
                #pragma unroll
                for (int ni = 0; ni < 4; ni++)
                    mma_bf16(acc[mi][ni], af[mi], bfg[ni]);
        }
        cur ^= 1;
    }

    // epilogue
    bf16* Cb = (seg == 0) ? C0 : ((seg == 1) ? C1 : C2);
    #pragma unroll
    for (int mi = 0; mi < 4; mi++) {
        #pragma unroll
        for (int ni = 0; ni < 4; ni++) {
            int col = wn + ni * 8 + 2 * tig;
            #pragma unroll
            for (int half = 0; half < 2; half++) {
                int row = bm + wm + mi * 16 + gid + half * 8;
                float v0 = acc[mi][ni][half * 2 + 0];
                float v1 = acc[mi][ni][half * 2 + 1];
                if (MODE == 2) {
                    int bidx = row >> 11;
                    int gc = bn + col;
                    float2 xv = *(const float2*)(X + (size_t)row * DD + gc);
                    float2 gv = *(const float2*)(gate + bidx * DD + gc);
                    float2 r;
                    r.x = xv.x + gv.x * v0;
                    r.y = xv.y + gv.y * v1;
                    *(float2*)(Cf + (size_t)row * DD + gc) = r;
                } else {
                    unsigned pk = packbf(v0, v1);
                    *(unsigned*)(Cb + (size_t)row * DD + coln + col) = pk;
                }
            }
        }
    }
}

// ---------------------------------------------------------------------------
// RoPE (in-place, bf16)
// ---------------------------------------------------------------------------
__global__ void rope_qk(bf16* __restrict__ q, bf16* __restrict__ k,
                        const float* __restrict__ rope) {
    int idx = blockIdx.x * 256 + threadIdx.x;
    int dh = idx & 31;
    int h  = (idx >> 5) & 15;
    int n  = (idx >> 9) & 2047;
    int b  = idx >> 20;
    int base = ((b * NN + n) * DD) + h * HD + dh;

    float a1 = rope[n * HD + dh];
    float a2 = rope[n * HD + dh + 32];
    float c1 = cosf(a1), s1 = sinf(a1);
    float c2 = cosf(a2), s2 = sinf(a2);

    float q1 = __bfloat162float(q[base]), q2 = __bfloat162float(q[base + 32]);
    q[base]      = __float2bfloat16_rn(q1 * c1 - q2 * s1);
    q[base + 32] = __float2bfloat16_rn(q2 * c2 + q1 * s2);

    float k1 = __bfloat162float(k[base]), k2 = __bfloat162float(k[base + 32]);
    k[base]      = __float2bfloat16_rn(k1 * c1 - k2 * s1);
    k[base + 32] = __float2bfloat16_rn(k2 * c2 + k1 * s2);
}

// ---------------------------------------------------------------------------
// Flash attention, bf16 mma. grid (N/64, H, B), 128 threads (4 warps).
// Warp owns 16 Q rows. KV double-buffered via cp.async.
// P stays in registers (C-frag of S == A-frag of PV after bf16 packing).
// ---------------------------------------------------------------------------
#define QSTR 72    // halves: 64 + 8 pad

__global__ __launch_bounds__(128)
void attn_kernel(const bf16* __restrict__ q, const bf16* __restrict__ k,
                 const bf16* __restrict__ v, bf16* __restrict__ o) {
    __shared__ bf16 Qs[64 * QSTR];
    __shared__ bf16 Ks[2][64 * QSTR];
    __shared__ bf16 Vs[2][64 * QSTR];

    const int qt = blockIdx.x, h = blockIdx.y, b = blockIdx.z;
    const int tid = threadIdx.x;
    const int warp = tid >> 5, lane = tid & 31;
    const int gid = lane >> 2, tig = lane & 3;
    const int hoff = h * HD;
    const size_t bbase = (size_t)b * NN * DD;

    auto issue_kv = [&](int kt, int st) {
        #pragma unroll
        for (int i = 0; i < 4; i++) {
            int idx = tid + i * 128;
            int r = idx >> 3, ch = idx & 7;
            size_t g = bbase + (size_t)(kt * 64 + r) * DD + hoff + ch * 8;
            cp16(&Ks[st][r * QSTR + ch * 8], &k[g]);
            cp16(&Vs[st][r * QSTR + ch * 8], &v[g]);
        }
    };

    // group 0: Q tile + KV tile 0
    #pragma unroll
    for (int i = 0; i < 4; i++) {
        int idx = tid + i * 128;
        int r = idx >> 3, ch = idx & 7;
        cp16(&Qs[r * QSTR + ch * 8],
             &q[bbase + (size_t)(qt * 64 + r) * DD + hoff + ch * 8]);
    }
    issue_kv(0, 0);
    CP_COMMIT;

    unsigned qa[4][4];
    float m_i[2] = {-1e30f, -1e30f};
    float l_i[2] = {0.0f, 0.0f};
    float O[8][4];
    #pragma unroll
    for (int ni = 0; ni < 8; ni++)
        #pragma unroll
        for (int r = 0; r < 4; r++) O[ni][r] = 0.0f;

    for (int kt = 0; kt < NN / 64; kt++) {
        int buf = kt & 1;
        if (kt + 1 < NN / 64) {
            issue_kv(kt + 1, buf ^ 1);
            CP_COMMIT;
            CP_WAIT(1);
        } else {
            CP_WAIT(0);
        }
        __syncthreads();

        if (kt == 0) {
            #pragma unroll
            for (int kk = 0; kk < 4; kk++) {
                int row = warp * 16 + (lane & 15);
                int col = kk * 16 + 8 * (lane >> 4);
                ldsm_x4(qa[kk][0], qa[kk][1], qa[kk][2], qa[kk][3],
                        &Qs[row * QSTR + col]);
            }
        }

        const bf16* ks = Ks[buf];
        const bf16* vs = Vs[buf];

        // ---- S = Q K^T ----
        float S[8][4];
        #pragma unroll
        for (int ni = 0; ni < 8; ni++)
            #pragma unroll
            for (int r = 0; r < 4; r++) S[ni][r] = 0.0f;
        #pragma unroll
        for (int kk = 0; kk < 4; kk++) {
            #pragma unroll
            for (int nj = 0; nj < 4; nj++) {
                // Ks is n-major: non-trans x4 gives col-major B frags
                int row = nj * 16 + (lane & 7) + 8 * (lane >> 4);
                int col = kk * 16 + 8 * ((lane >> 3) & 1);
                unsigned r0, r1, r2, r3;
                ldsm_x4(r0, r1, r2, r3, &ks[row * QSTR + col]);
                unsigned b0[2] = {r0, r1}, b1[2] = {r2, r3};
                mma_bf16(S[nj * 2],     qa[kk], b0);
                mma_bf16(S[nj * 2 + 1], qa[kk], b1);
            }
        }
        #pragma unroll
        for (int ni = 0; ni < 8; ni++)
            #pragma unroll
            for (int r = 0; r < 4; r++) S[ni][r] *= 0.125f;

        // ---- online softmax ----
        #pragma unroll
        for (int half = 0; half < 2; half++) {
            float mx = -1e30f;
            #pragma unroll
            for (int ni = 0; ni < 8; ni++)
                mx = fmaxf(mx, fmaxf(S[ni][half * 2], S[ni][half * 2 + 1]));
            mx = fmaxf(mx, __shfl_xor_sync(0xffffffffu, mx, 1));
            mx = fmaxf(mx, __shfl_xor_sync(0xffffffffu, mx, 2));
            float mnew = fmaxf(m_i[half], mx);
            float fac = __expf(m_i[half] - mnew);
            float rs = 0.0f;
            #pragma unroll
            for (int ni = 0; ni < 8; ni++) {
                float p0 = __expf(S[ni][half * 2]     - mnew);
                float p1 = __expf(S[ni][half * 2 + 1] - mnew);
                S[ni][half * 2]     = p0;
                S[ni][half * 2 + 1] = p1;
                rs += p0 + p1;
            }
            rs += __shfl_xor_sync(0xffffffffu, rs, 1);
            rs += __shfl_xor_sync(0xffffffffu, rs, 2);
            l_i[half] = l_i[half] * fac + rs;
            m_i[half] = mnew;
            #pragma unroll
            for (int ni = 0; ni < 8; ni++) {
                O[ni][half * 2]     *= fac;
                O[ni][half * 2 + 1] *= fac;
            }
        }

        // ---- pack P into A-fragments (register-only; layouts match) ----
        unsigned pa[4][4];
        #pragma unroll
        for (int kk2 = 0; kk2 < 4; kk2++) {
            pa[kk2][0] = packbf(S[2 * kk2][0],     S[2 * kk2][1]);
            pa[kk2][1] = packbf(S[2 * kk2][2],     S[2 * kk2][3]);
            pa[kk2][2] = packbf(S[2 * kk2 + 1][0], S[2 * kk2 + 1][1]);
            pa[kk2][3] = packbf(S[2 * kk2 + 1][2], S[2 * kk2 + 1][3]);
        }

        // ---- O += P V ----
        #pragma unroll
        for (int kk2 = 0; kk2 < 4; kk2++) {
            #pragma unroll
            for (int nj = 0; nj < 4; nj++) {
                // Vs is k-major: trans x4 gives col-major B frags
                int row = kk2 * 16 + (lane & 7) + 8 * ((lane >> 3) & 1);
                int col = nj * 16 + 8 * (lane >> 4);
                unsigned r0, r1, r2, r3;
                ldsm_x4t(r0, r1, r2, r3, &vs[row * QSTR + col]);
                unsigned b0[2] = {r0, r1}, b1[2] = {r2, r3};
                mma_bf16(O[nj * 2],     pa[kk2], b0);
                mma_bf16(O[nj * 2 + 1], pa[kk2], b1);
            }
        }
        __syncthreads();   // done reading buf before it is refilled
    }

    // ---- epilogue: normalize, bf16 store ----
    float inv0 = 1.0f / l_i[0], inv1 = 1.0f / l_i[1];
    #pragma unroll
    for (int ni = 0; ni < 8; ni++) {
        int col = hoff + ni * 8 + 2 * tig;
        int row0 = qt * 64 + warp * 16 + gid;
        *(unsigned*)(o + bbase + (size_t)row0 * DD + col) =
            packbf(O[ni][0] * inv0, O[ni][1] * inv0);
        *(unsigned*)(o + bbase + (size_t)(row0 + 8) * DD + col) =
            packbf(O[ni][2] * inv1, O[ni][3] * inv1);
    }
}

// ---------------------------------------------------------------------------
// Launcher
// ---------------------------------------------------------------------------
extern "C" void kernel_launch(void* const* d_in, const int* in_sizes, int n_in,
                              void* d_out, int out_size) {
    const float* x     = (const float*)d_in[0];
    const float* emb   = (const float*)d_in[1];
    const float* gate  = (const float*)d_in[2];
    // d_in[3] = crossattn_emb: unused by the reference
    const float* rope  = (const float*)d_in[4];
    const float* Wq1   = (const float*)d_in[5];
    const float* Wq2   = (const float*)d_in[6];
    const float* Wk1   = (const float*)d_in[7];
    const float* Wk2   = (const float*)d_in[8];
    const float* Wv    = (const float*)d_in[9];
    const float* Wo    = (const float*)d_in[10];
    const float* Wada1 = (const float*)d_in[11];
    const float* Wada2 = (const float*)d_in[12];
    const float* bada2 = (const float*)d_in[13];
    float* out = (float*)d_out;

    bf16 *xn_p, *t0q_p, *t0k_p, *q_p, *k_p, *v_p, *ao_p, *w1_p, *w2_p, *wo_p;
    float *h_p, *ada_p;
    cudaGetSymbolAddress((void**)&xn_p,  g_xn);
    cudaGetSymbolAddress((void**)&t0q_p, g_t0q);
    cudaGetSymbolAddress((void**)&t0k_p, g_t0k);
    cudaGetSymbolAddress((void**)&q_p,   g_q);
    cudaGetSymbolAddress((void**)&k_p,   g_k);
    cudaGetSymbolAddress((void**)&v_p,   g_v);
    cudaGetSymbolAddress((void**)&ao_p,  g_ao);
    cudaGetSymbolAddress((void**)&h_p,   g_h);
    cudaGetSymbolAddress((void**)&ada_p, g_ada);
    cudaGetSymbolAddress((void**)&w1_p,  g_w1);
    cudaGetSymbolAddress((void**)&w2_p,  g_w2);
    cudaGetSymbolAddress((void**)&wo_p,  g_wo);

    // pack weights (fp32 -> bf16, fused layouts)
    pack_w<<<1024, 256>>>(Wq1, w1_p, 3 * DD, 0);
    pack_w<<<1024, 256>>>(Wk1, w1_p, 3 * DD, DD);
    pack_w<<<1024, 256>>>(Wv,  w1_p, 3 * DD, 2 * DD);
    pack_w<<<1024, 256>>>(Wq2, w2_p, 2 * DD, 0);
    pack_w<<<1024, 256>>>(Wk2, w2_p, 2 * DD, DD);
    pack_w<<<1024, 256>>>(Wo,  wo_p, DD, 0);

    // adaLN modulation
    ada_fc1<<<dim3(4, 2), 256>>>(emb, Wada1, h_p);
    ada_fc2<<<dim3(8, 2), 256>>>(h_p, Wada2, bada2, ada_p);

    // LayerNorm + scale/shift -> bf16
    ln_mod<<<MM, 256>>>(x, ada_p, xn_p);

    // GEMM 1: xn @ [Wq1|Wk1|Wv]  -> t0q, t0k, v
    tgemm<0><<<dim3(24, 32), 256>>>(xn_p, nullptr, w1_p, 3 * DD,
                                    t0q_p, t0k_p, v_p, nullptr, nullptr, nullptr);
    // GEMM 2: [t0q|t0k] @ [Wq2|Wk2] -> q, k
    tgemm<1><<<dim3(16, 32), 256>>>(t0q_p, t0k_p, w2_p, 2 * DD,
                                    q_p, k_p, nullptr, nullptr, nullptr, nullptr);
    // RoPE (in place)
    rope_qk<<<(BB * NN * HH * 32) / 256, 256>>>(q_p, k_p, rope);

    // Attention
    attn_kernel<<<dim3(NN / 64, HH, BB), 128>>>(q_p, k_p, v_p, ao_p);

    // GEMM 3: out = x + gate * (ao @ Wo)
    tgemm<2><<<dim3(8, 32), 256>>>(ao_p, nullptr, wo_p, DD,
                                   nullptr, nullptr, nullptr, out, x, gate);
}

// round 10
// speedup vs baseline: 10.2788x; 1.0162x over previous
#include <cuda_runtime.h>
#include <cuda_bf16.h>
#include <math.h>

// ---------------------------------------------------------------------------
// Problem constants
// ---------------------------------------------------------------------------
#define BB 2
#define NN 2048
#define DD 1024
#define HH 16
#define HD 64
#define MM (BB * NN)          // 4096 rows flattened
#define ELEMS (MM * DD)

typedef __nv_bfloat16 bf16;

// ---------------------------------------------------------------------------
// Scratch (static device globals; no allocation allowed)
// ---------------------------------------------------------------------------
__device__ bf16  g_xn [ELEMS];
__device__ bf16  g_t0q[ELEMS];
__device__ bf16  g_t0k[ELEMS];
__device__ bf16  g_q  [ELEMS];
__device__ bf16  g_k  [ELEMS];
__device__ bf16  g_v  [ELEMS];
__device__ bf16  g_ao [ELEMS];
__device__ float g_h  [BB * DD];
__device__ float g_ada[BB * 2 * DD];
__device__ bf16  g_w1 [DD * 3 * DD];   // [1024][3072] = Wq1 | Wk1 | Wv
__device__ bf16  g_w2 [DD * 2 * DD];   // [1024][2048] = Wq2 | Wk2
__device__ bf16  g_wo [DD * DD];       // [1024][1024]

// ---------------------------------------------------------------------------
// PTX helpers
// ---------------------------------------------------------------------------
__device__ __forceinline__ void cp16(void* s, const void* g) {
    unsigned sa = (unsigned)__cvta_generic_to_shared(s);
    asm volatile("cp.async.cg.shared.global [%0], [%1], 16;" :: "r"(sa), "l"(g));
}
#define CP_COMMIT  asm volatile("cp.async.commit_group;")
#define CP_WAIT(n) asm volatile("cp.async.wait_group %0;" :: "n"(n))

__device__ __forceinline__ void ldsm_x4(unsigned& r0, unsigned& r1, unsigned& r2,
                                        unsigned& r3, const void* p) {
    unsigned a = (unsigned)__cvta_generic_to_shared(p);
    asm volatile("ldmatrix.sync.aligned.m8n8.x4.shared.b16 {%0,%1,%2,%3}, [%4];"
                 : "=r"(r0), "=r"(r1), "=r"(r2), "=r"(r3) : "r"(a));
}
__device__ __forceinline__ void ldsm_x4t(unsigned& r0, unsigned& r1, unsigned& r2,
                                         unsigned& r3, const void* p) {
    unsigned a = (unsigned)__cvta_generic_to_shared(p);
    asm volatile("ldmatrix.sync.aligned.m8n8.x4.trans.shared.b16 {%0,%1,%2,%3}, [%4];"
                 : "=r"(r0), "=r"(r1), "=r"(r2), "=r"(r3) : "r"(a));
}
__device__ __forceinline__ void mma_bf16(float* c, const unsigned* a,
                                         const unsigned* b) {
    asm volatile(
        "mma.sync.aligned.m16n8k16.row.col.f32.bf16.bf16.f32 "
        "{%0,%1,%2,%3}, {%4,%5,%6,%7}, {%8,%9}, {%0,%1,%2,%3};"
        : "+f"(c[0]), "+f"(c[1]), "+f"(c[2]), "+f"(c[3])
        : "r"(a[0]), "r"(a[1]), "r"(a[2]), "r"(a[3]), "r"(b[0]), "r"(b[1]));
}
__device__ __forceinline__ unsigned packbf(float a, float b) {
    __nv_bfloat162 t = __floats2bfloat162_rn(a, b);
    return *reinterpret_cast<unsigned*>(&t);
}

// ---------------------------------------------------------------------------
// Fused weight pack: all 6 weights in one launch. grid (1024, 6)
// ---------------------------------------------------------------------------
__global__ void pack_all(const float* __restrict__ Wq1, const float* __restrict__ Wk1,
                         const float* __restrict__ Wv,  const float* __restrict__ Wq2,
                         const float* __restrict__ Wk2, const float* __restrict__ Wo,
                         bf16* __restrict__ w1, bf16* __restrict__ w2,
                         bf16* __restrict__ wo) {
    const float* src; bf16* dst; int ld, col0;
    switch (blockIdx.y) {
        case 0:  src = Wq1; dst = w1; ld = 3 * DD; col0 = 0;      break;
        case 1:  src = Wk1; dst = w1; ld = 3 * DD; col0 = DD;     break;
        case 2:  src = Wv;  dst = w1; ld = 3 * DD; col0 = 2 * DD; break;
        case 3:  src = Wq2; dst = w2; ld = 2 * DD; col0 = 0;      break;
        case 4:  src = Wk2; dst = w2; ld = 2 * DD; col0 = DD;     break;
        default: src = Wo;  dst = wo; ld = DD;     col0 = 0;      break;
    }
    int idx = blockIdx.x * 256 + threadIdx.x;
    int r = idx >> 8;
    int c = (idx & 255) * 4;
    float4 v = *(const float4*)(src + r * 1024 + c);
    bf16* d = dst + (size_t)r * ld + col0 + c;
    *(__nv_bfloat162*)(d)     = __floats2bfloat162_rn(v.x, v.y);
    *(__nv_bfloat162*)(d + 2) = __floats2bfloat162_rn(v.z, v.w);
}

// ---------------------------------------------------------------------------
// adaLN (tiny, fp32)
// ---------------------------------------------------------------------------
__global__ void ada_fc1(const float* __restrict__ emb, const float* __restrict__ W,
                        float* __restrict__ h) {
    int b = blockIdx.y;
    int o = blockIdx.x * 256 + threadIdx.x;
    __shared__ float se[DD];
    for (int i = threadIdx.x; i < DD; i += 256) {
        float e = emb[b * DD + i];
        se[i] = e / (1.0f + expf(-e));
    }
    __syncthreads();
    float acc = 0.0f;
    #pragma unroll 8
    for (int i = 0; i < DD; i++) acc += se[i] * W[i * DD + o];
    h[b * DD + o] = acc;
}

__global__ void ada_fc2(const float* __restrict__ h, const float* __restrict__ W,
                        const float* __restrict__ bias, float* __restrict__ ada) {
    int b = blockIdx.y;
    int o = blockIdx.x * 256 + threadIdx.x;
    __shared__ float sh[DD];
    for (int i = threadIdx.x; i < DD; i += 256) sh[i] = h[b * DD + i];
    __syncthreads();
    float acc = bias[o];
    #pragma unroll 8
    for (int i = 0; i < DD; i++) acc += sh[i] * W[i * (2 * DD) + o];
    ada[b * 2 * DD + o] = acc;
}

// ---------------------------------------------------------------------------
// LayerNorm + adaLN scale/shift -> bf16
// ---------------------------------------------------------------------------
__global__ void ln_mod(const float* __restrict__ x, const float* __restrict__ ada,
                       bf16* __restrict__ xn) {
    int row = blockIdx.x;
    int b = row >> 11;
    int tid = threadIdx.x;
    const float* xr = x + (size_t)row * DD;

    float4 xv = *(const float4*)(xr + tid * 4);
    float s  = xv.x + xv.y + xv.z + xv.w;
    float s2 = xv.x * xv.x + xv.y * xv.y + xv.z * xv.z + xv.w * xv.w;
    #pragma unroll
    for (int off = 16; off; off >>= 1) {
        s  += __shfl_xor_sync(0xffffffffu, s,  off);
        s2 += __shfl_xor_sync(0xffffffffu, s2, off);
    }
    __shared__ float rs[8], rs2[8];
    int wid = tid >> 5, lane = tid & 31;
    if (lane == 0) { rs[wid] = s; rs2[wid] = s2; }
    __syncthreads();
    float S = 0.f, S2 = 0.f;
    #pragma unroll
    for (int w = 0; w < 8; w++) { S += rs[w]; S2 += rs2[w]; }
    float mu  = S * (1.0f / DD);
    float var = S2 * (1.0f / DD) - mu * mu;
    float rinv = rsqrtf(var + 1e-6f);

    int c = tid * 4;
    float4 sc  = *(const float4*)(ada + b * 2 * DD + DD + c);
    float4 shv = *(const float4*)(ada + b * 2 * DD + c);
    float o0 = (xv.x - mu) * rinv * (1.0f + sc.x) + shv.x;
    float o1 = (xv.y - mu) * rinv * (1.0f + sc.y) + shv.y;
    float o2 = (xv.z - mu) * rinv * (1.0f + sc.z) + shv.z;
    float o3 = (xv.w - mu) * rinv * (1.0f + sc.w) + shv.w;
    uint2 st;
    st.x = packbf(o0, o1);
    st.y = packbf(o2, o3);
    *(uint2*)(xn + (size_t)row * DD + c) = st;
}

// ---------------------------------------------------------------------------
// bf16 tensor-core GEMM, 4-stage cp.async pipeline.
// 128x128x32 block tile, 8 warps (2x4), warp 64x32, m16n8k16 + ldmatrix.
// MODE 0: C = bf16(A@B), 3 col segments -> C0/C1/C2 (QKV pack)
// MODE 1: dual A (seg0->Aa, seg1->Ab), 2 segments -> C0/C1
// MODE 2: Cf = X + gate * (A@B)  (fp32 gated-residual epilogue)
// ---------------------------------------------------------------------------
#define ASTR 40    // halves: 32 + 8 pad
#define BSTR 136   // halves: 128 + 8 pad
#define GSTAGES 4
#define GEMM_SMEM (GSTAGES * (128 * ASTR + 32 * BSTR) * 2)

template <int MODE>
__global__ __launch_bounds__(256, 2)
void tgemm(const bf16* __restrict__ Aa, const bf16* __restrict__ Ab,
           const bf16* __restrict__ B, int ldb,
           bf16* __restrict__ C0, bf16* __restrict__ C1, bf16* __restrict__ C2,
           float* __restrict__ Cf, const float* __restrict__ X,
           const float* __restrict__ gate) {
    extern __shared__ bf16 smg[];
    bf16* Asm = smg;                            // GSTAGES x 128*ASTR
    bf16* Bsm = smg + GSTAGES * 128 * ASTR;     // GSTAGES x 32*BSTR

    const int bm = blockIdx.y * 128;
    const int bn = blockIdx.x * 128;
    const int seg = bn >> 10;
    const int coln = bn & 1023;
    const bf16* A = (MODE == 1 && seg == 1) ? Ab : Aa;

    const int tid = threadIdx.x;
    const int warp = tid >> 5, lane = tid & 31;
    const int gid = lane >> 2, tig = lane & 3;
    const int wm = (warp >> 2) * 64;
    const int wn = (warp & 3) * 32;

    float acc[4][4][4];
    #pragma unroll
    for (int mi = 0; mi < 4; mi++)
        #pragma unroll
        for (int ni = 0; ni < 4; ni++)
            #pragma unroll
            for (int r = 0; r < 4; r++) acc[mi][ni][r] = 0.0f;

    auto issue = [&](int st, int k0) {
        bf16* as = Asm + st * 128 * ASTR;
        bf16* bs = Bsm + st * 32 * BSTR;
        #pragma unroll
        for (int i = 0; i < 2; i++) {
            int idx = tid + i * 256;
            int ar = idx >> 2, ach = idx & 3;
            cp16(&as[ar * ASTR + ach * 8],
                 &A[(size_t)(bm + ar) * DD + k0 + ach * 8]);
            int br = idx >> 4, bch = idx & 15;
            cp16(&bs[br * BSTR + bch * 8],
                 &B[(size_t)(k0 + br) * ldb + bn + bch * 8]);
        }
    };

    // prologue: 3-deep prefetch
    #pragma unroll
    for (int s = 0; s < 3; s++) { issue(s, s * 32); CP_COMMIT; }

    for (int kt = 0; kt < DD / 32; kt++) {
        CP_WAIT(2);            // FIFO: everything up through stage kt resident
        __syncthreads();       // all warps past compute kt-1; stage visible
        if (kt + 3 < DD / 32) issue((kt + 3) & 3, (kt + 3) * 32);
        CP_COMMIT;             // unconditional: keeps group count uniform

        const bf16* as = Asm + (kt & 3) * 128 * ASTR;
        const bf16* bs = Bsm + (kt & 3) * 32 * BSTR;
        #pragma unroll
        for (int kk = 0; kk < 2; kk++) {
            unsigned af[4][4], bfg[4][2];
            #pragma unroll
            for (int mi = 0; mi < 4; mi++) {
                int row = wm + mi * 16 + (lane & 15);
                int col = kk * 16 + 8 * (lane >> 4);
                ldsm_x4(af[mi][0], af[mi][1], af[mi][2], af[mi][3],
                        &as[row * ASTR + col]);
            }
            #pragma unroll
            for (int nj = 0; nj < 2; nj++) {
                int row = kk * 16 + (lane & 7) + 8 * ((lane >> 3) & 1);
                int col = wn + nj * 16 + 8 * (lane >> 4);
                unsigned r0, r1, r2, r3;
                ldsm_x4t(r0, r1, r2, r3, &bs[row * BSTR + col]);
                bfg[nj * 2][0] = r0; bfg[nj * 2][1] = r1;
                bfg[nj * 2 + 1][0] = r2; bfg[nj * 2 + 1][1] = r3;
            }
            #pragma unroll
            for (int mi = 0; mi < 4; mi++)
                #pragma unroll
                for (int ni = 0; ni < 4; ni++)
                    mma_bf16(acc[mi][ni], af[mi], bfg[ni]);
        }
    }

    // epilogue
    bf16* Cb = (seg == 0) ? C0 : ((seg == 1) ? C1 : C2);
    #pragma unroll
    for (int mi = 0; mi < 4; mi++) {
        #pragma unroll
        for (int ni = 0; ni < 4; ni++) {
            int col = wn + ni * 8 + 2 * tig;
            #pragma unroll
            for (int half = 0; half < 2; half++) {
                int row = bm + wm + mi * 16 + gid + half * 8;
                float v0 = acc[mi][ni][half * 2 + 0];
                float v1 = acc[mi][ni][half * 2 + 1];
                if (MODE == 2) {
                    int bidx = row >> 11;
                    int gc = bn + col;
                    float2 xv = *(const float2*)(X + (size_t)row * DD + gc);
                    float2 gv = *(const float2*)(gate + bidx * DD + gc);
                    float2 r;
                    r.x = xv.x + gv.x * v0;
                    r.y = xv.y + gv.y * v1;
                    *(float2*)(Cf + (size_t)row * DD + gc) = r;
                } else {
                    unsigned pk = packbf(v0, v1);
                    *(unsigned*)(Cb + (size_t)row * DD + coln + col) = pk;
                }
            }
        }
    }
}

// ---------------------------------------------------------------------------
// RoPE (in-place, bf16)
// ---------------------------------------------------------------------------
__global__ void rope_qk(bf16* __restrict__ q, bf16* __restrict__ k,
                        const float* __restrict__ rope) {
    int idx = blockIdx.x * 256 + threadIdx.x;
    int dh = idx & 31;
    int h  = (idx >> 5) & 15;
    int n  = (idx >> 9) & 2047;
    int b  = idx >> 20;
    int base = ((b * NN + n) * DD) + h * HD + dh;

    float a1 = rope[n * HD + dh];
    float a2 = rope[n * HD + dh + 32];
    float c1 = cosf(a1), s1 = sinf(a1);
    float c2 = cosf(a2), s2 = sinf(a2);

    float q1 = __bfloat162float(q[base]), q2 = __bfloat162float(q[base + 32]);
    q[base]      = __float2bfloat16_rn(q1 * c1 - q2 * s1);
    q[base + 32] = __float2bfloat16_rn(q2 * c2 + q1 * s2);

    float k1 = __bfloat162float(k[base]), k2 = __bfloat162float(k[base + 32]);
    k[base]      = __float2bfloat16_rn(k1 * c1 - k2 * s1);
    k[base + 32] = __float2bfloat16_rn(k2 * c2 + k1 * s2);
}

// ---------------------------------------------------------------------------
// Flash attention, bf16 mma. grid (N/128, H, B), 256 threads (8 warps).
// 128-row Q tile per CTA (halves L2 KV traffic vs 64-row tiles).
// 3-stage KV ring (2-deep cp.async prefetch). P stays in registers.
// ---------------------------------------------------------------------------
#define QSTR 72    // halves: 64 + 8 pad
#define ATTN_SMEM ((128 * QSTR + 6 * 64 * QSTR) * 2)

__global__ __launch_bounds__(256)
void attn_kernel(const bf16* __restrict__ q, const bf16* __restrict__ k,
                 const bf16* __restrict__ v, bf16* __restrict__ o) {
    extern __shared__ bf16 sma[];
    bf16* Qs  = sma;                 // 128 x QSTR
    bf16* KVs = sma + 128 * QSTR;    // 3 stages x (K 64xQSTR, V 64xQSTR)

    const int qt = blockIdx.x, h = blockIdx.y, b = blockIdx.z;
    const int tid = threadIdx.x;
    const int warp = tid >> 5, lane = tid & 31;
    const int gid = lane >> 2, tig = lane & 3;
    const int hoff = h * HD;
    const size_t bbase = (size_t)b * NN * DD;

    auto issue_kv = [&](int kt, int st) {
        bf16* Ks = KVs + st * 2 * 64 * QSTR;
        bf16* Vs = Ks + 64 * QSTR;
        #pragma unroll
        for (int i = 0; i < 2; i++) {
            int idx = tid + i * 256;
            int r = idx >> 3, ch = idx & 7;
            size_t g = bbase + (size_t)(kt * 64 + r) * DD + hoff + ch * 8;
            cp16(&Ks[r * QSTR + ch * 8], &k[g]);
            cp16(&Vs[r * QSTR + ch * 8], &v[g]);
        }
    };

    // prologue: Q tile + KV0 in group 0, KV1 in group 1
    #pragma unroll
    for (int i = 0; i < 4; i++) {
        int idx = tid + i * 256;
        int r = idx >> 3, ch = idx & 7;
        cp16(&Qs[r * QSTR + ch * 8],
             &q[bbase + (size_t)(qt * 128 + r) * DD + hoff + ch * 8]);
    }
    issue_kv(0, 0);
    CP_COMMIT;
    issue_kv(1, 1);
    CP_COMMIT;

    unsigned qa[4][4];
    float m_i[2] = {-1e30f, -1e30f};
    float l_i[2] = {0.0f, 0.0f};
    float O[8][4];
    #pragma unroll
    for (int ni = 0; ni < 8; ni++)
        #pragma unroll
        for (int r = 0; r < 4; r++) O[ni][r] = 0.0f;

    for (int kt = 0; kt < NN / 64; kt++) {
        CP_WAIT(1);          // FIFO: group kt complete
        __syncthreads();     // all warps past compute kt-1 (buf reuse safe)
        if (kt + 2 < NN / 64) issue_kv(kt + 2, (kt + 2) % 3);
        CP_COMMIT;

        if (kt == 0) {
            #pragma unroll
            for (int kk = 0; kk < 4; kk++) {
                int row = warp * 16 + (lane & 15);
                int col = kk * 16 + 8 * (lane >> 4);
                ldsm_x4(qa[kk][0], qa[kk][1], qa[kk][2], qa[kk][3],
                        &Qs[row * QSTR + col]);
            }
        }

        const bf16* ks = KVs + (kt % 3) * 2 * 64 * QSTR;
        const bf16* vs = ks + 64 * QSTR;

        // ---- S = Q K^T ----
        float S[8][4];
        #pragma unroll
        for (int ni = 0; ni < 8; ni++)
            #pragma unroll
            for (int r = 0; r < 4; r++) S[ni][r] = 0.0f;
        #pragma unroll
        for (int kk = 0; kk < 4; kk++) {
            #pragma unroll
            for (int nj = 0; nj < 4; nj++) {
                int row = nj * 16 + (lane & 7) + 8 * (lane >> 4);
                int col = kk * 16 + 8 * ((lane >> 3) & 1);
                unsigned r0, r1, r2, r3;
                ldsm_x4(r0, r1, r2, r3, &ks[row * QSTR + col]);
                unsigned b0[2] = {r0, r1}, b1[2] = {r2, r3};
                mma_bf16(S[nj * 2],     qa[kk], b0);
                mma_bf16(S[nj * 2 + 1], qa[kk], b1);
            }
        }
        #pragma unroll
        for (int ni = 0; ni < 8; ni++)
            #pragma unroll
            for (int r = 0; r < 4; r++) S[ni][r] *= 0.125f;

        // ---- online softmax ----
        #pragma unroll
        for (int half = 0; half < 2; half++) {
            float mx = -1e30f;
            #pragma unroll
            for (int ni = 0; ni < 8; ni++)
                mx = fmaxf(mx, fmaxf(S[ni][half * 2], S[ni][half * 2 + 1]));
            mx = fmaxf(mx, __shfl_xor_sync(0xffffffffu, mx, 1));
            mx = fmaxf(mx, __shfl_xor_sync(0xffffffffu, mx, 2));
            float mnew = fmaxf(m_i[half], mx);
            float fac = __expf(m_i[half] - mnew);
            float rs = 0.0f;
            #pragma unroll
            for (int ni = 0; ni < 8; ni++) {
                float p0 = __expf(S[ni][half * 2]     - mnew);
                float p1 = __expf(S[ni][half * 2 + 1] - mnew);
                S[ni][half * 2]     = p0;
                S[ni][half * 2 + 1] = p1;
                rs += p0 + p1;
            }
            rs += __shfl_xor_sync(0xffffffffu, rs, 1);
            rs += __shfl_xor_sync(0xffffffffu, rs, 2);
            l_i[half] = l_i[half] * fac + rs;
            m_i[half] = mnew;
            #pragma unroll
            for (int ni = 0; ni < 8; ni++) {
                O[ni][half * 2]     *= fac;
                O[ni][half * 2 + 1] *= fac;
            }
        }

        // ---- pack P into A-fragments (register-only) ----
        unsigned pa[4][4];
        #pragma unroll
        for (int kk2 = 0; kk2 < 4; kk2++) {
            pa[kk2][0] = packbf(S[2 * kk2][0],     S[2 * kk2][1]);
            pa[kk2][1] = packbf(S[2 * kk2][2],     S[2 * kk2][3]);
            pa[kk2][2] = packbf(S[2 * kk2 + 1][0], S[2 * kk2 + 1][1]);
            pa[kk2][3] = packbf(S[2 * kk2 + 1][2], S[2 * kk2 + 1][3]);
        }

        // ---- O += P V ----
        #pragma unroll
        for (int kk2 = 0; kk2 < 4; kk2++) {
            #pragma unroll
            for (int nj = 0; nj < 4; nj++) {
                int row = kk2 * 16 + (lane & 7) + 8 * ((lane >> 3) & 1);
                int col = nj * 16 + 8 * (lane >> 4);
                unsigned r0, r1, r2, r3;
                ldsm_x4t(r0, r1, r2, r3, &vs[row * QSTR + col]);
                unsigned b0[2] = {r0, r1}, b1[2] = {r2, r3};
                mma_bf16(O[nj * 2],     pa[kk2], b0);
                mma_bf16(O[nj * 2 + 1], pa[kk2], b1);
            }
        }
    }

    // ---- epilogue: normalize, bf16 store ----
    float inv0 = 1.0f / l_i[0], inv1 = 1.0f / l_i[1];
    #pragma unroll
    for (int ni = 0; ni < 8; ni++) {
        int col = hoff + ni * 8 + 2 * tig;
        int row0 = qt * 128 + warp * 16 + gid;
        *(unsigned*)(o + bbase + (size_t)row0 * DD + col) =
            packbf(O[ni][0] * inv0, O[ni][1] * inv0);
        *(unsigned*)(o + bbase + (size_t)(row0 + 8) * DD + col) =
            packbf(O[ni][2] * inv1, O[ni][3] * inv1);
    }
}

// ---------------------------------------------------------------------------
// Launcher
// ---------------------------------------------------------------------------
extern "C" void kernel_launch(void* const* d_in, const int* in_sizes, int n_in,
                              void* d_out, int out_size) {
    const float* x     = (const float*)d_in[0];
    const float* emb   = (const float*)d_in[1];
    const float* gate  = (const float*)d_in[2];
    // d_in[3] = crossattn_emb: unused by the reference
    const float* rope  = (const float*)d_in[4];
    const float* Wq1   = (const float*)d_in[5];
    const float* Wq2   = (const float*)d_in[6];
    const float* Wk1   = (const float*)d_in[7];
    const float* Wk2   = (const float*)d_in[8];
    const float* Wv    = (const float*)d_in[9];
    const float* Wo    = (const float*)d_in[10];
    const float* Wada1 = (const float*)d_in[11];
    const float* Wada2 = (const float*)d_in[12];
    const float* bada2 = (const float*)d_in[13];
    float* out = (float*)d_out;

    bf16 *xn_p, *t0q_p, *t0k_p, *q_p, *k_p, *v_p, *ao_p, *w1_p, *w2_p, *wo_p;
    float *h_p, *ada_p;
    cudaGetSymbolAddress((void**)&xn_p,  g_xn);
    cudaGetSymbolAddress((void**)&t0q_p, g_t0q);
    cudaGetSymbolAddress((void**)&t0k_p, g_t0k);
    cudaGetSymbolAddress((void**)&q_p,   g_q);
    cudaGetSymbolAddress((void**)&k_p,   g_k);
    cudaGetSymbolAddress((void**)&v_p,   g_v);
    cudaGetSymbolAddress((void**)&ao_p,  g_ao);
    cudaGetSymbolAddress((void**)&h_p,   g_h);
    cudaGetSymbolAddress((void**)&ada_p, g_ada);
    cudaGetSymbolAddress((void**)&w1_p,  g_w1);
    cudaGetSymbolAddress((void**)&w2_p,  g_w2);
    cudaGetSymbolAddress((void**)&wo_p,  g_wo);

    cudaFuncSetAttribute(tgemm<0>, cudaFuncAttributeMaxDynamicSharedMemorySize, GEMM_SMEM);
    cudaFuncSetAttribute(tgemm<1>, cudaFuncAttributeMaxDynamicSharedMemorySize, GEMM_SMEM);
    cudaFuncSetAttribute(tgemm<2>, cudaFuncAttributeMaxDynamicSharedMemorySize, GEMM_SMEM);
    cudaFuncSetAttribute(attn_kernel, cudaFuncAttributeMaxDynamicSharedMemorySize, ATTN_SMEM);

    // pack all weights (one launch)
    pack_all<<<dim3(1024, 6), 256>>>(Wq1, Wk1, Wv, Wq2, Wk2, Wo,
                                     w1_p, w2_p, wo_p);

    // adaLN modulation
    ada_fc1<<<dim3(4, 2), 256>>>(emb, Wada1, h_p);
    ada_fc2<<<dim3(8, 2), 256>>>(h_p, Wada2, bada2, ada_p);

    // LayerNorm + scale/shift -> bf16
    ln_mod<<<MM, 256>>>(x, ada_p, xn_p);

    // GEMM 1: xn @ [Wq1|Wk1|Wv]  -> t0q, t0k, v
    tgemm<0><<<dim3(24, 32), 256, GEMM_SMEM>>>(xn_p, nullptr, w1_p, 3 * DD,
                                    t0q_p, t0k_p, v_p, nullptr, nullptr, nullptr);
    // GEMM 2: [t0q|t0k] @ [Wq2|Wk2] -> q, k
    tgemm<1><<<dim3(16, 32), 256, GEMM_SMEM>>>(t0q_p, t0k_p, w2_p, 2 * DD,
                                    q_p, k_p, nullptr, nullptr, nullptr, nullptr);
    // RoPE (in place)
    rope_qk<<<(BB * NN * HH * 32) / 256, 256>>>(q_p, k_p, rope);

    // Attention (128-row Q tiles, 3-stage KV pipeline)
    attn_kernel<<<dim3(NN / 128, HH, BB), 256, ATTN_SMEM>>>(q_p, k_p, v_p, ao_p);

    // GEMM 3: out = x + gate * (ao @ Wo)
    tgemm<2><<<dim3(8, 32), 256, GEMM_SMEM>>>(ao_p, nullptr, wo_p, DD,
                                   nullptr, nullptr, nullptr, out, x, gate);
}

// round 14
// speedup vs baseline: 10.4487x; 1.0165x over previous
#include <cuda_runtime.h>
#include <cuda_bf16.h>
#include <math.h>

// ---------------------------------------------------------------------------
// Problem constants
// ---------------------------------------------------------------------------
#define BB 2
#define NN 2048
#define DD 1024
#define HH 16
#define HD 64
#define MM (BB * NN)
#define ELEMS (MM * DD)

typedef __nv_bfloat16 bf16;

// ---------------------------------------------------------------------------
// Scratch (static device globals; no allocation allowed)
// ---------------------------------------------------------------------------
__device__ bf16  g_xn [ELEMS];
__device__ bf16  g_t0q[ELEMS];
__device__ bf16  g_t0k[ELEMS];
__device__ bf16  g_q  [ELEMS];
__device__ bf16  g_k  [ELEMS];
__device__ bf16  g_v  [ELEMS];
__device__ bf16  g_ao [ELEMS];
__device__ float g_h  [BB * DD];
__device__ float g_ada[BB * 2 * DD];
__device__ bf16  g_w1 [DD * 3 * DD];   // [1024][3072] = Wq1 | Wk1 | Wv
__device__ bf16  g_w2 [DD * 2 * DD];   // [1024][2048] = Wq2 | Wk2
__device__ bf16  g_wo [DD * DD];       // [1024][1024]

// ---------------------------------------------------------------------------
// PTX helpers (legacy mma.sync path only — tcgen05 rejected by this toolchain)
// ---------------------------------------------------------------------------
__device__ __forceinline__ void cp16(void* s, const void* g) {
    unsigned sa = (unsigned)__cvta_generic_to_shared(s);
    asm volatile("cp.async.cg.shared.global [%0], [%1], 16;" :: "r"(sa), "l"(g));
}
#define CP_COMMIT  asm volatile("cp.async.commit_group;")
#define CP_WAIT(n) asm volatile("cp.async.wait_group %0;" :: "n"(n))

__device__ __forceinline__ void ldsm_x4(unsigned& r0, unsigned& r1, unsigned& r2,
                                        unsigned& r3, const void* p) {
    unsigned a = (unsigned)__cvta_generic_to_shared(p);
    asm volatile("ldmatrix.sync.aligned.m8n8.x4.shared.b16 {%0,%1,%2,%3}, [%4];"
                 : "=r"(r0), "=r"(r1), "=r"(r2), "=r"(r3) : "r"(a));
}
__device__ __forceinline__ void ldsm_x4t(unsigned& r0, unsigned& r1, unsigned& r2,
                                         unsigned& r3, const void* p) {
    unsigned a = (unsigned)__cvta_generic_to_shared(p);
    asm volatile("ldmatrix.sync.aligned.m8n8.x4.trans.shared.b16 {%0,%1,%2,%3}, [%4];"
                 : "=r"(r0), "=r"(r1), "=r"(r2), "=r"(r3) : "r"(a));
}
__device__ __forceinline__ void mma_bf16(float* c, const unsigned* a,
                                         const unsigned* b) {
    asm volatile(
        "mma.sync.aligned.m16n8k16.row.col.f32.bf16.bf16.f32 "
        "{%0,%1,%2,%3}, {%4,%5,%6,%7}, {%8,%9}, {%0,%1,%2,%3};"
        : "+f"(c[0]), "+f"(c[1]), "+f"(c[2]), "+f"(c[3])
        : "r"(a[0]), "r"(a[1]), "r"(a[2]), "r"(a[3]), "r"(b[0]), "r"(b[1]));
}
__device__ __forceinline__ unsigned packbf(float a, float b) {
    __nv_bfloat162 t = __floats2bfloat162_rn(a, b);
    return *reinterpret_cast<unsigned*>(&t);
}

// ---------------------------------------------------------------------------
// Fused weight pack: all 6 weights in one launch. grid (1024, 6)
// ---------------------------------------------------------------------------
__global__ void pack_all(const float* __restrict__ Wq1, const float* __restrict__ Wk1,
                         const float* __restrict__ Wv,  const float* __restrict__ Wq2,
                         const float* __restrict__ Wk2, const float* __restrict__ Wo,
                         bf16* __restrict__ w1, bf16* __restrict__ w2,
                         bf16* __restrict__ wo) {
    const float* src; bf16* dst; int ld, col0;
    switch (blockIdx.y) {
        case 0:  src = Wq1; dst = w1; ld = 3 * DD; col0 = 0;      break;
        case 1:  src = Wk1; dst = w1; ld = 3 * DD; col0 = DD;     break;
        case 2:  src = Wv;  dst = w1; ld = 3 * DD; col0 = 2 * DD; break;
        case 3:  src = Wq2; dst = w2; ld = 2 * DD; col0 = 0;      break;
        case 4:  src = Wk2; dst = w2; ld = 2 * DD; col0 = DD;     break;
        default: src = Wo;  dst = wo; ld = DD;     col0 = 0;      break;
    }
    int idx = blockIdx.x * 256 + threadIdx.x;
    int r = idx >> 8;
    int c = (idx & 255) * 4;
    float4 v = *(const float4*)(src + r * 1024 + c);
    bf16* d = dst + (size_t)r * ld + col0 + c;
    *(__nv_bfloat162*)(d)     = __floats2bfloat162_rn(v.x, v.y);
    *(__nv_bfloat162*)(d + 2) = __floats2bfloat162_rn(v.z, v.w);
}

// ---------------------------------------------------------------------------
// adaLN (tiny, fp32)
// ---------------------------------------------------------------------------
__global__ void ada_fc1(const float* __restrict__ emb, const float* __restrict__ W,
                        float* __restrict__ h) {
    int b = blockIdx.y;
    int o = blockIdx.x * 256 + threadIdx.x;
    __shared__ float se[DD];
    for (int i = threadIdx.x; i < DD; i += 256) {
        float e = emb[b * DD + i];
        se[i] = e / (1.0f + expf(-e));
    }
    __syncthreads();
    float acc = 0.0f;
    #pragma unroll 8
    for (int i = 0; i < DD; i++) acc += se[i] * W[i * DD + o];
    h[b * DD + o] = acc;
}

__global__ void ada_fc2(const float* __restrict__ h, const float* __restrict__ W,
                        const float* __restrict__ bias, float* __restrict__ ada) {
    int b = blockIdx.y;
    int o = blockIdx.x * 256 + threadIdx.x;
    __shared__ float sh[DD];
    for (int i = threadIdx.x; i < DD; i += 256) sh[i] = h[b * DD + i];
    __syncthreads();
    float acc = bias[o];
    #pragma unroll 8
    for (int i = 0; i < DD; i++) acc += sh[i] * W[i * (2 * DD) + o];
    ada[b * 2 * DD + o] = acc;
}

// ---------------------------------------------------------------------------
// LayerNorm + adaLN scale/shift -> bf16
// ---------------------------------------------------------------------------
__global__ void ln_mod(const float* __restrict__ x, const float* __restrict__ ada,
                       bf16* __restrict__ xn) {
    int row = blockIdx.x;
    int b = row >> 11;
    int tid = threadIdx.x;
    const float* xr = x + (size_t)row * DD;

    float4 xv = *(const float4*)(xr + tid * 4);
    float s  = xv.x + xv.y + xv.z + xv.w;
    float s2 = xv.x * xv.x + xv.y * xv.y + xv.z * xv.z + xv.w * xv.w;
    #pragma unroll
    for (int off = 16; off; off >>= 1) {
        s  += __shfl_xor_sync(0xffffffffu, s,  off);
        s2 += __shfl_xor_sync(0xffffffffu, s2, off);
    }
    __shared__ float rs[8], rs2[8];
    int wid = tid >> 5, lane = tid & 31;
    if (lane == 0) { rs[wid] = s; rs2[wid] = s2; }
    __syncthreads();
    float S = 0.f, S2 = 0.f;
    #pragma unroll
    for (int w = 0; w < 8; w++) { S += rs[w]; S2 += rs2[w]; }
    float mu  = S * (1.0f / DD);
    float var = S2 * (1.0f / DD) - mu * mu;
    float rinv = rsqrtf(var + 1e-6f);

    int c = tid * 4;
    float4 sc  = *(const float4*)(ada + b * 2 * DD + DD + c);
    float4 shv = *(const float4*)(ada + b * 2 * DD + c);
    float o0 = (xv.x - mu) * rinv * (1.0f + sc.x) + shv.x;
    float o1 = (xv.y - mu) * rinv * (1.0f + sc.y) + shv.y;
    float o2 = (xv.z - mu) * rinv * (1.0f + sc.z) + shv.z;
    float o3 = (xv.w - mu) * rinv * (1.0f + sc.w) + shv.w;
    uint2 st;
    st.x = packbf(o0, o1);
    st.y = packbf(o2, o3);
    *(uint2*)(xn + (size_t)row * DD + c) = st;
}

// ---------------------------------------------------------------------------
// bf16 tensor-core GEMM, 4-stage cp.async pipeline.
// 128x128x32 block tile, 8 warps (2x4), warp 64x32, m16n8k16 + ldmatrix.
// MODE 0: C = bf16(A@B), 3 col segments -> C0/C1/C2 (QKV pack)
// MODE 2: Cf = X + gate * (A@B)  (fp32 gated-residual epilogue)
// ---------------------------------------------------------------------------
#define ASTR 40    // halves: 32 + 8 pad
#define BSTR 136   // halves: 128 + 8 pad
#define GSTAGES 4
#define GEMM_SMEM (GSTAGES * (128 * ASTR + 32 * BSTR) * 2)

template <int MODE>
__global__ __launch_bounds__(256, 2)
void tgemm(const bf16* __restrict__ Aa,
           const bf16* __restrict__ B, int ldb,
           bf16* __restrict__ C0, bf16* __restrict__ C1, bf16* __restrict__ C2,
           float* __restrict__ Cf, const float* __restrict__ X,
           const float* __restrict__ gate) {
    extern __shared__ bf16 smg[];
    bf16* Asm = smg;
    bf16* Bsm = smg + GSTAGES * 128 * ASTR;

    const int bm = blockIdx.y * 128;
    const int bn = blockIdx.x * 128;
    const int seg = bn >> 10;
    const int coln = bn & 1023;
    const bf16* A = Aa;

    const int tid = threadIdx.x;
    const int warp = tid >> 5, lane = tid & 31;
    const int gid = lane >> 2, tig = lane & 3;
    const int wm = (warp >> 2) * 64;
    const int wn = (warp & 3) * 32;

    float acc[4][4][4];
    #pragma unroll
    for (int mi = 0; mi < 4; mi++)
        #pragma unroll
        for (int ni = 0; ni < 4; ni++)
            #pragma unroll
            for (int r = 0; r < 4; r++) acc[mi][ni][r] = 0.0f;

    auto issue = [&](int st, int k0) {
        bf16* as = Asm + st * 128 * ASTR;
        bf16* bs = Bsm + st * 32 * BSTR;
        #pragma unroll
        for (int i = 0; i < 2; i++) {
            int idx = tid + i * 256;
            int ar = idx >> 2, ach = idx & 3;
            cp16(&as[ar * ASTR + ach * 8],
                 &A[(size_t)(bm + ar) * DD + k0 + ach * 8]);
            int br = idx >> 4, bch = idx & 15;
            cp16(&bs[br * BSTR + bch * 8],
                 &B[(size_t)(k0 + br) * ldb + bn + bch * 8]);
        }
    };

    #pragma unroll
    for (int s = 0; s < 3; s++) { issue(s, s * 32); CP_COMMIT; }

    for (int kt = 0; kt < DD / 32; kt++) {
        CP_WAIT(2);
        __syncthreads();
        if (kt + 3 < DD / 32) issue((kt + 3) & 3, (kt + 3) * 32);
        CP_COMMIT;

        const bf16* as = Asm + (kt & 3) * 128 * ASTR;
        const bf16* bs = Bsm + (kt & 3) * 32 * BSTR;
        #pragma unroll
        for (int kk = 0; kk < 2; kk++) {
            unsigned af[4][4], bfg[4][2];
            #pragma unroll
            for (int mi = 0; mi < 4; mi++) {
                int row = wm + mi * 16 + (lane & 15);
                int col = kk * 16 + 8 * (lane >> 4);
                ldsm_x4(af[mi][0], af[mi][1], af[mi][2], af[mi][3],
                        &as[row * ASTR + col]);
            }
            #pragma unroll
            for (int nj = 0; nj < 2; nj++) {
                int row = kk * 16 + (lane & 7) + 8 * ((lane >> 3) & 1);
                int col = wn + nj * 16 + 8 * (lane >> 4);
                unsigned r0, r1, r2, r3;
                ldsm_x4t(r0, r1, r2, r3, &bs[row * BSTR + col]);
                bfg[nj * 2][0] = r0; bfg[nj * 2][1] = r1;
                bfg[nj * 2 + 1][0] = r2; bfg[nj * 2 + 1][1] = r3;
            }
            #pragma unroll
            for (int mi = 0; mi < 4; mi++)
                #pragma unroll
                for (int ni = 0; ni < 4; ni++)
                    mma_bf16(acc[mi][ni], af[mi], bfg[ni]);
        }
    }

    bf16* Cb = (seg == 0) ? C0 : ((seg == 1) ? C1 : C2);
    #pragma unroll
    for (int mi = 0; mi < 4; mi++) {
        #pragma unroll
        for (int ni = 0; ni < 4; ni++) {
            int col = wn + ni * 8 + 2 * tig;
            #pragma unroll
            for (int half = 0; half < 2; half++) {
                int row = bm + wm + mi * 16 + gid + half * 8;
                float v0 = acc[mi][ni][half * 2 + 0];
                float v1 = acc[mi][ni][half * 2 + 1];
                if (MODE == 2) {
                    int bidx = row >> 11;
                    int gc = bn + col;
                    float2 xv = *(const float2*)(X + (size_t)row * DD + gc);
                    float2 gv = *(const float2*)(gate + bidx * DD + gc);
                    float2 r;
                    r.x = xv.x + gv.x * v0;
                    r.y = xv.y + gv.y * v1;
                    *(float2*)(Cf + (size_t)row * DD + gc) = r;
                } else {
                    unsigned pk = packbf(v0, v1);
                    *(unsigned*)(Cb + (size_t)row * DD + coln + col) = pk;
                }
            }
        }
    }
}

// ---------------------------------------------------------------------------
// GEMM2 with fused RoPE epilogue. Warp tile 32x64 (4x2 warp grid) so that
// each thread's accumulator holds BOTH halves of every head pair (d, d+32):
// ni and ni+4 (head = 64 cols, warp tile N = 64, head-aligned).
// Dual-A: seg0 -> Aa (q path), seg1 -> Ab (k path). RoPE applied on fp32.
// ---------------------------------------------------------------------------
__global__ __launch_bounds__(256, 2)
void tgemm_rope(const bf16* __restrict__ Aa, const bf16* __restrict__ Ab,
                const bf16* __restrict__ B, int ldb,
                const float* __restrict__ rope,
                bf16* __restrict__ C0, bf16* __restrict__ C1) {
    extern __shared__ bf16 smg[];
    bf16* Asm = smg;
    bf16* Bsm = smg + GSTAGES * 128 * ASTR;

    const int bm = blockIdx.y * 128;
    const int bn = blockIdx.x * 128;
    const int seg = bn >> 10;
    const int coln = bn & 1023;
    const bf16* A = (seg == 1) ? Ab : Aa;

    const int tid = threadIdx.x;
    const int warp = tid >> 5, lane = tid & 31;
    const int gid = lane >> 2, tig = lane & 3;
    const int wm = (warp & 3) * 32;    // 4 row groups of 32
    const int wn = (warp >> 2) * 64;   // 2 col groups of 64 (head-aligned)

    float acc[2][8][4];
    #pragma unroll
    for (int mi = 0; mi < 2; mi++)
        #pragma unroll
        for (int ni = 0; ni < 8; ni++)
            #pragma unroll
            for (int r = 0; r < 4; r++) acc[mi][ni][r] = 0.0f;

    auto issue = [&](int st, int k0) {
        bf16* as = Asm + st * 128 * ASTR;
        bf16* bs = Bsm + st * 32 * BSTR;
        #pragma unroll
        for (int i = 0; i < 2; i++) {
            int idx = tid + i * 256;
            int ar = idx >> 2, ach = idx & 3;
            cp16(&as[ar * ASTR + ach * 8],
                 &A[(size_t)(bm + ar) * DD + k0 + ach * 8]);
            int br = idx >> 4, bch = idx & 15;
            cp16(&bs[br * BSTR + bch * 8],
                 &B[(size_t)(k0 + br) * ldb + bn + bch * 8]);
        }
    };

    #pragma unroll
    for (int s = 0; s < 3; s++) { issue(s, s * 32); CP_COMMIT; }

    for (int kt = 0; kt < DD / 32; kt++) {
        CP_WAIT(2);
        __syncthreads();
        if (kt + 3 < DD / 32) issue((kt + 3) & 3, (kt + 3) * 32);
        CP_COMMIT;

        const bf16* as = Asm + (kt & 3) * 128 * ASTR;
        const bf16* bs = Bsm + (kt & 3) * 32 * BSTR;
        #pragma unroll
        for (int kk = 0; kk < 2; kk++) {
            unsigned af[2][4], bfg[8][2];
            #pragma unroll
            for (int mi = 0; mi < 2; mi++) {
                int row = wm + mi * 16 + (lane & 15);
                int col = kk * 16 + 8 * (lane >> 4);
                ldsm_x4(af[mi][0], af[mi][1], af[mi][2], af[mi][3],
                        &as[row * ASTR + col]);
            }
            #pragma unroll
            for (int nj = 0; nj < 4; nj++) {
                int row = kk * 16 + (lane & 7) + 8 * ((lane >> 3) & 1);
                int col = wn + nj * 16 + 8 * (lane >> 4);
                unsigned r0, r1, r2, r3;
                ldsm_x4t(r0, r1, r2, r3, &bs[row * BSTR + col]);
                bfg[nj * 2][0] = r0; bfg[nj * 2][1] = r1;
                bfg[nj * 2 + 1][0] = r2; bfg[nj * 2 + 1][1] = r3;
            }
            #pragma unroll
            for (int mi = 0; mi < 2; mi++)
                #pragma unroll
                for (int ni = 0; ni < 8; ni++)
                    mma_bf16(acc[mi][ni], af[mi], bfg[ni]);
        }
    }

    // Fused RoPE epilogue (on fp32 accumulators), then bf16 store.
    bf16* Cb = (seg == 0) ? C0 : C1;
    #pragma unroll
    for (int mi = 0; mi < 2; mi++) {
        #pragma unroll
        for (int half = 0; half < 2; half++) {
            int row = bm + wm + mi * 16 + gid + half * 8;
            int n = row & (NN - 1);
            const float* rp = rope + (size_t)n * HD;
            #pragma unroll
            for (int ni = 0; ni < 4; ni++) {
                int d0 = ni * 8 + 2 * tig;         // in-head index, < 32
                float lo0 = acc[mi][ni][half * 2 + 0];
                float lo1 = acc[mi][ni][half * 2 + 1];
                float hi0 = acc[mi][ni + 4][half * 2 + 0];
                float hi1 = acc[mi][ni + 4][half * 2 + 1];
                float c10, s10, c11, s11, c20, s20, c21, s21;
                __sincosf(rp[d0],          &s10, &c10);
                __sincosf(rp[d0 + 1],      &s11, &c11);
                __sincosf(rp[d0 + 32],     &s20, &c20);
                __sincosf(rp[d0 + 33],     &s21, &c21);
                float q_lo0 = lo0 * c10 - hi0 * s10;
                float q_lo1 = lo1 * c11 - hi1 * s11;
                float q_hi0 = hi0 * c20 + lo0 * s20;
                float q_hi1 = hi1 * c21 + lo1 * s21;
                int gc = coln + wn + d0;
                *(unsigned*)(Cb + (size_t)row * DD + gc) = packbf(q_lo0, q_lo1);
                *(unsigned*)(Cb + (size_t)row * DD + gc + 32) = packbf(q_hi0, q_hi1);
            }
        }
    }
}

// ---------------------------------------------------------------------------
// Flash attention, bf16 mma. grid (N/128, H, B), 256 threads (8 warps).
// 128-row Q tile, 3-stage KV ring, P in registers, exp2-domain softmax.
// launch_bounds(256,2): cap regs at 128 to co-schedule 2 CTAs/SM.
// ---------------------------------------------------------------------------
#define QSTR 72
#define ATTN_SMEM ((128 * QSTR + 6 * 64 * QSTR) * 2)
#define SOFTMAX_SCALE 0.18033688f   // 0.125 * log2(e)

__global__ __launch_bounds__(256, 2)
void attn_kernel(const bf16* __restrict__ q, const bf16* __restrict__ k,
                 const bf16* __restrict__ v, bf16* __restrict__ o) {
    extern __shared__ bf16 sma[];
    bf16* Qs  = sma;
    bf16* KVs = sma + 128 * QSTR;

    const int qt = blockIdx.x, h = blockIdx.y, b = blockIdx.z;
    const int tid = threadIdx.x;
    const int warp = tid >> 5, lane = tid & 31;
    const int gid = lane >> 2, tig = lane & 3;
    const int hoff = h * HD;
    const size_t bbase = (size_t)b * NN * DD;

    auto issue_kv = [&](int kt, int st) {
        bf16* Ks = KVs + st * 2 * 64 * QSTR;
        bf16* Vs = Ks + 64 * QSTR;
        #pragma unroll
        for (int i = 0; i < 2; i++) {
            int idx = tid + i * 256;
            int r = idx >> 3, ch = idx & 7;
            size_t g = bbase + (size_t)(kt * 64 + r) * DD + hoff + ch * 8;
            cp16(&Ks[r * QSTR + ch * 8], &k[g]);
            cp16(&Vs[r * QSTR + ch * 8], &v[g]);
        }
    };

    #pragma unroll
    for (int i = 0; i < 4; i++) {
        int idx = tid + i * 256;
        int r = idx >> 3, ch = idx & 7;
        cp16(&Qs[r * QSTR + ch * 8],
             &q[bbase + (size_t)(qt * 128 + r) * DD + hoff + ch * 8]);
    }
    issue_kv(0, 0);
    CP_COMMIT;
    issue_kv(1, 1);
    CP_COMMIT;

    unsigned qa[4][4];
    float m_i[2] = {-1e30f, -1e30f};
    float l_i[2] = {0.0f, 0.0f};
    float O[8][4];
    #pragma unroll
    for (int ni = 0; ni < 8; ni++)
        #pragma unroll
        for (int r = 0; r < 4; r++) O[ni][r] = 0.0f;

    for (int kt = 0; kt < NN / 64; kt++) {
        CP_WAIT(1);
        __syncthreads();
        if (kt + 2 < NN / 64) issue_kv(kt + 2, (kt + 2) % 3);
        CP_COMMIT;

        if (kt == 0) {
            #pragma unroll
            for (int kk = 0; kk < 4; kk++) {
                int row = warp * 16 + (lane & 15);
                int col = kk * 16 + 8 * (lane >> 4);
                ldsm_x4(qa[kk][0], qa[kk][1], qa[kk][2], qa[kk][3],
                        &Qs[row * QSTR + col]);
            }
        }

        const bf16* ks = KVs + (kt % 3) * 2 * 64 * QSTR;
        const bf16* vs = ks + 64 * QSTR;

        float S[8][4];
        #pragma unroll
        for (int ni = 0; ni < 8; ni++)
            #pragma unroll
            for (int r = 0; r < 4; r++) S[ni][r] = 0.0f;
        #pragma unroll
        for (int kk = 0; kk < 4; kk++) {
            #pragma unroll
            for (int nj = 0; nj < 4; nj++) {
                int row = nj * 16 + (lane & 7) + 8 * (lane >> 4);
                int col = kk * 16 + 8 * ((lane >> 3) & 1);
                unsigned r0, r1, r2, r3;
                ldsm_x4(r0, r1, r2, r3, &ks[row * QSTR + col]);
                unsigned b0[2] = {r0, r1}, b1[2] = {r2, r3};
                mma_bf16(S[nj * 2],     qa[kk], b0);
                mma_bf16(S[nj * 2 + 1], qa[kk], b1);
            }
        }
        #pragma unroll
        for (int ni = 0; ni < 8; ni++)
            #pragma unroll
            for (int r = 0; r < 4; r++) S[ni][r] *= SOFTMAX_SCALE;

        // online softmax in exp2 domain
        #pragma unroll
        for (int half = 0; half < 2; half++) {
            float mx = -1e30f;
            #pragma unroll
            for (int ni = 0; ni < 8; ni++)
                mx = fmaxf(mx, fmaxf(S[ni][half * 2], S[ni][half * 2 + 1]));
            mx = fmaxf(mx, __shfl_xor_sync(0xffffffffu, mx, 1));
            mx = fmaxf(mx, __shfl_xor_sync(0xffffffffu, mx, 2));
            float mnew = fmaxf(m_i[half], mx);
            float fac = exp2f(m_i[half] - mnew);
            float rs = 0.0f;
            #pragma unroll
            for (int ni = 0; ni < 8; ni++) {
                float p0 = exp2f(S[ni][half * 2]     - mnew);
                float p1 = exp2f(S[ni][half * 2 + 1] - mnew);
                S[ni][half * 2]     = p0;
                S[ni][half * 2 + 1] = p1;
                rs += p0 + p1;
            }
            rs += __shfl_xor_sync(0xffffffffu, rs, 1);
            rs += __shfl_xor_sync(0xffffffffu, rs, 2);
            l_i[half] = l_i[half] * fac + rs;
            m_i[half] = mnew;
            #pragma unroll
            for (int ni = 0; ni < 8; ni++) {
                O[ni][half * 2]     *= fac;
                O[ni][half * 2 + 1] *= fac;
            }
        }

        unsigned pa[4][4];
        #pragma unroll
        for (int kk2 = 0; kk2 < 4; kk2++) {
            pa[kk2][0] = packbf(S[2 * kk2][0],     S[2 * kk2][1]);
            pa[kk2][1] = packbf(S[2 * kk2][2],     S[2 * kk2][3]);
            pa[kk2][2] = packbf(S[2 * kk2 + 1][0], S[2 * kk2 + 1][1]);
            pa[kk2][3] = packbf(S[2 * kk2 + 1][2], S[2 * kk2 + 1][3]);
        }

        #pragma unroll
        for (int kk2 = 0; kk2 < 4; kk2++) {
            #pragma unroll
            for (int nj = 0; nj < 4; nj++) {
                int row = kk2 * 16 + (lane & 7) + 8 * ((lane >> 3) & 1);
                int col = nj * 16 + 8 * (lane >> 4);
                unsigned r0, r1, r2, r3;
                ldsm_x4t(r0, r1, r2, r3, &vs[row * QSTR + col]);
                unsigned b0[2] = {r0, r1}, b1[2] = {r2, r3};
                mma_bf16(O[nj * 2],     pa[kk2], b0);
                mma_bf16(O[nj * 2 + 1], pa[kk2], b1);
            }
        }
    }

    float inv0 = 1.0f / l_i[0], inv1 = 1.0f / l_i[1];
    #pragma unroll
    for (int ni = 0; ni < 8; ni++) {
        int col = hoff + ni * 8 + 2 * tig;
        int row0 = qt * 128 + warp * 16 + gid;
        *(unsigned*)(o + bbase + (size_t)row0 * DD + col) =
            packbf(O[ni][0] * inv0, O[ni][1] * inv0);
        *(unsigned*)(o + bbase + (size_t)(row0 + 8) * DD + col) =
            packbf(O[ni][2] * inv1, O[ni][3] * inv1);
    }
}

// ---------------------------------------------------------------------------
// Launcher
// ---------------------------------------------------------------------------
extern "C" void kernel_launch(void* const* d_in, const int* in_sizes, int n_in,
                              void* d_out, int out_size) {
    const float* x     = (const float*)d_in[0];
    const float* emb   = (const float*)d_in[1];
    const float* gate  = (const float*)d_in[2];
    // d_in[3] = crossattn_emb: unused by the reference
    const float* rope  = (const float*)d_in[4];
    const float* Wq1   = (const float*)d_in[5];
    const float* Wq2   = (const float*)d_in[6];
    const float* Wk1   = (const float*)d_in[7];
    const float* Wk2   = (const float*)d_in[8];
    const float* Wv    = (const float*)d_in[9];
    const float* Wo    = (const float*)d_in[10];
    const float* Wada1 = (const float*)d_in[11];
    const float* Wada2 = (const float*)d_in[12];
    const float* bada2 = (const float*)d_in[13];
    float* out = (float*)d_out;

    bf16 *xn_p, *t0q_p, *t0k_p, *q_p, *k_p, *v_p, *ao_p, *w1_p, *w2_p, *wo_p;
    float *h_p, *ada_p;
    cudaGetSymbolAddress((void**)&xn_p,  g_xn);
    cudaGetSymbolAddress((void**)&t0q_p, g_t0q);
    cudaGetSymbolAddress((void**)&t0k_p, g_t0k);
    cudaGetSymbolAddress((void**)&q_p,   g_q);
    cudaGetSymbolAddress((void**)&k_p,   g_k);
    cudaGetSymbolAddress((void**)&v_p,   g_v);
    cudaGetSymbolAddress((void**)&ao_p,  g_ao);
    cudaGetSymbolAddress((void**)&h_p,   g_h);
    cudaGetSymbolAddress((void**)&ada_p, g_ada);
    cudaGetSymbolAddress((void**)&w1_p,  g_w1);
    cudaGetSymbolAddress((void**)&w2_p,  g_w2);
    cudaGetSymbolAddress((void**)&wo_p,  g_wo);

    cudaFuncSetAttribute(tgemm<0>, cudaFuncAttributeMaxDynamicSharedMemorySize, GEMM_SMEM);
    cudaFuncSetAttribute(tgemm<2>, cudaFuncAttributeMaxDynamicSharedMemorySize, GEMM_SMEM);
    cudaFuncSetAttribute(tgemm_rope, cudaFuncAttributeMaxDynamicSharedMemorySize, GEMM_SMEM);
    cudaFuncSetAttribute(attn_kernel, cudaFuncAttributeMaxDynamicSharedMemorySize, ATTN_SMEM);

    // pack all weights (one launch)
    pack_all<<<dim3(1024, 6), 256>>>(Wq1, Wk1, Wv, Wq2, Wk2, Wo,
                                     w1_p, w2_p, wo_p);

    // adaLN modulation
    ada_fc1<<<dim3(4, 2), 256>>>(emb, Wada1, h_p);
    ada_fc2<<<dim3(8, 2), 256>>>(h_p, Wada2, bada2, ada_p);

    // LayerNorm + scale/shift -> bf16
    ln_mod<<<MM, 256>>>(x, ada_p, xn_p);

    // GEMM 1: xn @ [Wq1|Wk1|Wv]  -> t0q, t0k, v
    tgemm<0><<<dim3(24, 32), 256, GEMM_SMEM>>>(xn_p, w1_p, 3 * DD,
                                    t0q_p, t0k_p, v_p, nullptr, nullptr, nullptr);
    // GEMM 2 + fused RoPE: [t0q|t0k] @ [Wq2|Wk2] -> q, k (rotated)
    tgemm_rope<<<dim3(16, 32), 256, GEMM_SMEM>>>(t0q_p, t0k_p, w2_p, 2 * DD,
                                                 rope, q_p, k_p);

    // Attention (128-row Q tiles, 3-stage KV pipeline, 2 CTAs/SM)
    attn_kernel<<<dim3(NN / 128, HH, BB), 256, ATTN_SMEM>>>(q_p, k_p, v_p, ao_p);

    // GEMM 3: out = x + gate * (ao @ Wo)
    tgemm<2><<<dim3(8, 32), 256, GEMM_SMEM>>>(ao_p, wo_p, DD,
                                   nullptr, nullptr, nullptr, out, x, gate);
}

// round 15
// speedup vs baseline: 11.4305x; 1.0940x over previous
#include <cuda_runtime.h>
#include <cuda_bf16.h>
#include <math.h>

// ---------------------------------------------------------------------------
// Problem constants
// ---------------------------------------------------------------------------
#define BB 2
#define NN 2048
#define DD 1024
#define HH 16
#define HD 64
#define MM (BB * NN)
#define ELEMS (MM * DD)

typedef __nv_bfloat16 bf16;

// ---------------------------------------------------------------------------
// Scratch (static device globals; no allocation allowed)
// ---------------------------------------------------------------------------
__device__ bf16  g_xn [ELEMS];
__device__ bf16  g_tmp[4 * DD * DD];   // bf16 Wq1|Wq2|Wk1|Wk2 staging
__device__ bf16  g_q  [ELEMS];
__device__ bf16  g_k  [ELEMS];
__device__ bf16  g_v  [ELEMS];
__device__ bf16  g_ao [ELEMS];
__device__ float g_h  [BB * DD];
__device__ float g_ada[BB * 2 * DD];
__device__ bf16  g_w1 [DD * 3 * DD];   // [1024][3072] = Wq12 | Wk12 | Wv
__device__ bf16  g_wo [DD * DD];       // [1024][1024]

// ---------------------------------------------------------------------------
// PTX helpers (legacy mma.sync path — tcgen05 rejected by this toolchain)
// ---------------------------------------------------------------------------
__device__ __forceinline__ void cp16(void* s, const void* g) {
    unsigned sa = (unsigned)__cvta_generic_to_shared(s);
    asm volatile("cp.async.cg.shared.global [%0], [%1], 16;" :: "r"(sa), "l"(g));
}
#define CP_COMMIT  asm volatile("cp.async.commit_group;")
#define CP_WAIT(n) asm volatile("cp.async.wait_group %0;" :: "n"(n))

__device__ __forceinline__ void ldsm_x4(unsigned& r0, unsigned& r1, unsigned& r2,
                                        unsigned& r3, const void* p) {
    unsigned a = (unsigned)__cvta_generic_to_shared(p);
    asm volatile("ldmatrix.sync.aligned.m8n8.x4.shared.b16 {%0,%1,%2,%3}, [%4];"
                 : "=r"(r0), "=r"(r1), "=r"(r2), "=r"(r3) : "r"(a));
}
__device__ __forceinline__ void ldsm_x4t(unsigned& r0, unsigned& r1, unsigned& r2,
                                         unsigned& r3, const void* p) {
    unsigned a = (unsigned)__cvta_generic_to_shared(p);
    asm volatile("ldmatrix.sync.aligned.m8n8.x4.trans.shared.b16 {%0,%1,%2,%3}, [%4];"
                 : "=r"(r0), "=r"(r1), "=r"(r2), "=r"(r3) : "r"(a));
}
__device__ __forceinline__ void mma_bf16(float* c, const unsigned* a,
                                         const unsigned* b) {
    asm volatile(
        "mma.sync.aligned.m16n8k16.row.col.f32.bf16.bf16.f32 "
        "{%0,%1,%2,%3}, {%4,%5,%6,%7}, {%8,%9}, {%0,%1,%2,%3};"
        : "+f"(c[0]), "+f"(c[1]), "+f"(c[2]), "+f"(c[3])
        : "r"(a[0]), "r"(a[1]), "r"(a[2]), "r"(a[3]), "r"(b[0]), "r"(b[1]));
}
__device__ __forceinline__ unsigned packbf(float a, float b) {
    __nv_bfloat162 t = __floats2bfloat162_rn(a, b);
    return *reinterpret_cast<unsigned*>(&t);
}

// ---------------------------------------------------------------------------
// Pack: Wq1,Wq2,Wk1,Wk2 -> bf16 staging; Wv -> w1 seg2; Wo -> wo. grid(1024,6)
// ---------------------------------------------------------------------------
__global__ void pack_all(const float* __restrict__ Wq1, const float* __restrict__ Wq2,
                         const float* __restrict__ Wk1, const float* __restrict__ Wk2,
                         const float* __restrict__ Wv,  const float* __restrict__ Wo,
                         bf16* __restrict__ tmp, bf16* __restrict__ w1,
                         bf16* __restrict__ wo) {
    const float* src; bf16* dst; int ld, col0;
    switch (blockIdx.y) {
        case 0:  src = Wq1; dst = tmp;                ld = DD;     col0 = 0;      break;
        case 1:  src = Wq2; dst = tmp + 1 * DD * DD;  ld = DD;     col0 = 0;      break;
        case 2:  src = Wk1; dst = tmp + 2 * DD * DD;  ld = DD;     col0 = 0;      break;
        case 3:  src = Wk2; dst = tmp + 3 * DD * DD;  ld = DD;     col0 = 0;      break;
        case 4:  src = Wv;  dst = w1;                 ld = 3 * DD; col0 = 2 * DD; break;
        default: src = Wo;  dst = wo;                 ld = DD;     col0 = 0;      break;
    }
    int idx = blockIdx.x * 256 + threadIdx.x;
    int r = idx >> 8;
    int c = (idx & 255) * 4;
    float4 v = *(const float4*)(src + r * 1024 + c);
    bf16* d = dst + (size_t)r * ld + col0 + c;
    *(__nv_bfloat162*)(d)     = __floats2bfloat162_rn(v.x, v.y);
    *(__nv_bfloat162*)(d + 2) = __floats2bfloat162_rn(v.z, v.w);
}

// ---------------------------------------------------------------------------
// adaLN (tiny, fp32)
// ---------------------------------------------------------------------------
__global__ void ada_fc1(const float* __restrict__ emb, const float* __restrict__ W,
                        float* __restrict__ h) {
    int b = blockIdx.y;
    int o = blockIdx.x * 256 + threadIdx.x;
    __shared__ float se[DD];
    for (int i = threadIdx.x; i < DD; i += 256) {
        float e = emb[b * DD + i];
        se[i] = e / (1.0f + expf(-e));
    }
    __syncthreads();
    float acc = 0.0f;
    #pragma unroll 8
    for (int i = 0; i < DD; i++) acc += se[i] * W[i * DD + o];
    h[b * DD + o] = acc;
}

__global__ void ada_fc2(const float* __restrict__ h, const float* __restrict__ W,
                        const float* __restrict__ bias, float* __restrict__ ada) {
    int b = blockIdx.y;
    int o = blockIdx.x * 256 + threadIdx.x;
    __shared__ float sh[DD];
    for (int i = threadIdx.x; i < DD; i += 256) sh[i] = h[b * DD + i];
    __syncthreads();
    float acc = bias[o];
    #pragma unroll 8
    for (int i = 0; i < DD; i++) acc += sh[i] * W[i * (2 * DD) + o];
    ada[b * 2 * DD + o] = acc;
}

// ---------------------------------------------------------------------------
// LayerNorm + adaLN scale/shift -> bf16
// ---------------------------------------------------------------------------
__global__ void ln_mod(const float* __restrict__ x, const float* __restrict__ ada,
                       bf16* __restrict__ xn) {
    int row = blockIdx.x;
    int b = row >> 11;
    int tid = threadIdx.x;
    const float* xr = x + (size_t)row * DD;

    float4 xv = *(const float4*)(xr + tid * 4);
    float s  = xv.x + xv.y + xv.z + xv.w;
    float s2 = xv.x * xv.x + xv.y * xv.y + xv.z * xv.z + xv.w * xv.w;
    #pragma unroll
    for (int off = 16; off; off >>= 1) {
        s  += __shfl_xor_sync(0xffffffffu, s,  off);
        s2 += __shfl_xor_sync(0xffffffffu, s2, off);
    }
    __shared__ float rs[8], rs2[8];
    int wid = tid >> 5, lane = tid & 31;
    if (lane == 0) { rs[wid] = s; rs2[wid] = s2; }
    __syncthreads();
    float S = 0.f, S2 = 0.f;
    #pragma unroll
    for (int w = 0; w < 8; w++) { S += rs[w]; S2 += rs2[w]; }
    float mu  = S * (1.0f / DD);
    float var = S2 * (1.0f / DD) - mu * mu;
    float rinv = rsqrtf(var + 1e-6f);

    int c = tid * 4;
    float4 sc  = *(const float4*)(ada + b * 2 * DD + DD + c);
    float4 shv = *(const float4*)(ada + b * 2 * DD + c);
    float o0 = (xv.x - mu) * rinv * (1.0f + sc.x) + shv.x;
    float o1 = (xv.y - mu) * rinv * (1.0f + sc.y) + shv.y;
    float o2 = (xv.z - mu) * rinv * (1.0f + sc.z) + shv.z;
    float o3 = (xv.w - mu) * rinv * (1.0f + sc.w) + shv.w;
    uint2 st;
    st.x = packbf(o0, o1);
    st.y = packbf(o2, o3);
    *(uint2*)(xn + (size_t)row * DD + c) = st;
}

// ---------------------------------------------------------------------------
// Shared GEMM tile parameters
// ---------------------------------------------------------------------------
#define ASTR 40    // halves: 32 + 8 pad
#define BSTR 136   // halves: 128 + 8 pad
#define GSTAGES 4
#define GEMM_SMEM (GSTAGES * (128 * ASTR + 32 * BSTR) * 2)

// ---------------------------------------------------------------------------
// Weight-combine GEMM: Wq12 = bWq1 @ bWq2, Wk12 = bWk1 @ bWk2  (M=N=K=1024)
// grid (16, 8): mat = bx>>3 (0:q, 1:k), output into w1 segs 0/1 (ld 3072).
// Same 128x128x32 pipeline / 64x32 warp tiles as the main GEMMs.
// ---------------------------------------------------------------------------
__global__ __launch_bounds__(256, 2)
void wgemm(const bf16* __restrict__ T, bf16* __restrict__ w1) {
    extern __shared__ bf16 smg[];
    bf16* Asm = smg;
    bf16* Bsm = smg + GSTAGES * 128 * ASTR;

    const int mat  = blockIdx.x >> 3;
    const int coln = (blockIdx.x & 7) * 128;
    const int bm   = blockIdx.y * 128;
    const bf16* A = T + (size_t)mat * 2 * DD * DD;            // Wq1 or Wk1
    const bf16* B = T + (size_t)mat * 2 * DD * DD + DD * DD;  // Wq2 or Wk2

    const int tid = threadIdx.x;
    const int warp = tid >> 5, lane = tid & 31;
    const int gid = lane >> 2, tig = lane & 3;
    const int wm = (warp >> 2) * 64;
    const int wn = (warp & 3) * 32;

    float acc[4][4][4];
    #pragma unroll
    for (int mi = 0; mi < 4; mi++)
        #pragma unroll
        for (int ni = 0; ni < 4; ni++)
            #pragma unroll
            for (int r = 0; r < 4; r++) acc[mi][ni][r] = 0.0f;

    auto issue = [&](int st, int k0) {
        bf16* as = Asm + st * 128 * ASTR;
        bf16* bs = Bsm + st * 32 * BSTR;
        #pragma unroll
        for (int i = 0; i < 2; i++) {
            int idx = tid + i * 256;
            int ar = idx >> 2, ach = idx & 3;
            cp16(&as[ar * ASTR + ach * 8],
                 &A[(size_t)(bm + ar) * DD + k0 + ach * 8]);
            int br = idx >> 4, bch = idx & 15;
            cp16(&bs[br * BSTR + bch * 8],
                 &B[(size_t)(k0 + br) * DD + coln + bch * 8]);
        }
    };

    #pragma unroll
    for (int s = 0; s < 3; s++) { issue(s, s * 32); CP_COMMIT; }

    for (int kt = 0; kt < DD / 32; kt++) {
        CP_WAIT(2);
        __syncthreads();
        if (kt + 3 < DD / 32) issue((kt + 3) & 3, (kt + 3) * 32);
        CP_COMMIT;

        const bf16* as = Asm + (kt & 3) * 128 * ASTR;
        const bf16* bs = Bsm + (kt & 3) * 32 * BSTR;
        #pragma unroll
        for (int kk = 0; kk < 2; kk++) {
            unsigned af[4][4], bfg[4][2];
            #pragma unroll
            for (int mi = 0; mi < 4; mi++) {
                int row = wm + mi * 16 + (lane & 15);
                int col = kk * 16 + 8 * (lane >> 4);
                ldsm_x4(af[mi][0], af[mi][1], af[mi][2], af[mi][3],
                        &as[row * ASTR + col]);
            }
            #pragma unroll
            for (int nj = 0; nj < 2; nj++) {
                int row = kk * 16 + (lane & 7) + 8 * ((lane >> 3) & 1);
                int col = wn + nj * 16 + 8 * (lane >> 4);
                unsigned r0, r1, r2, r3;
                ldsm_x4t(r0, r1, r2, r3, &bs[row * BSTR + col]);
                bfg[nj * 2][0] = r0; bfg[nj * 2][1] = r1;
                bfg[nj * 2 + 1][0] = r2; bfg[nj * 2 + 1][1] = r3;
            }
            #pragma unroll
            for (int mi = 0; mi < 4; mi++)
                #pragma unroll
                for (int ni = 0; ni < 4; ni++)
                    mma_bf16(acc[mi][ni], af[mi], bfg[ni]);
        }
    }

    bf16* dst = w1 + (size_t)mat * DD;   // seg column offset in [1024][3072]
    #pragma unroll
    for (int mi = 0; mi < 4; mi++) {
        #pragma unroll
        for (int ni = 0; ni < 4; ni++) {
            int col = coln + wn + ni * 8 + 2 * tig;
            #pragma unroll
            for (int half = 0; half < 2; half++) {
                int row = bm + wm + mi * 16 + gid + half * 8;
                *(unsigned*)(dst + (size_t)row * (3 * DD) + col) =
                    packbf(acc[mi][ni][half * 2], acc[mi][ni][half * 2 + 1]);
            }
        }
    }
}

// ---------------------------------------------------------------------------
// Fused QKV GEMM + RoPE: [q|k|v] = xn @ [Wq12|Wk12|Wv], RoPE on q/k segs.
// grid (24, 32). Warp tile 32x64 (head-aligned) so each thread owns both
// halves of every RoPE pair (ni, ni+4).
// ---------------------------------------------------------------------------
__global__ __launch_bounds__(256, 2)
void qkv_rope(const bf16* __restrict__ A, const bf16* __restrict__ B,
              const float* __restrict__ rope,
              bf16* __restrict__ Cq, bf16* __restrict__ Ck,
              bf16* __restrict__ Cv) {
    extern __shared__ bf16 smg[];
    bf16* Asm = smg;
    bf16* Bsm = smg + GSTAGES * 128 * ASTR;

    const int bm = blockIdx.y * 128;
    const int bn = blockIdx.x * 128;
    const int seg = bn >> 10;
    const int coln = bn & 1023;

    const int tid = threadIdx.x;
    const int warp = tid >> 5, lane = tid & 31;
    const int gid = lane >> 2, tig = lane & 3;
    const int wm = (warp & 3) * 32;    // 4 row groups of 32
    const int wn = (warp >> 2) * 64;   // 2 col groups of 64 (head-aligned)

    float acc[2][8][4];
    #pragma unroll
    for (int mi = 0; mi < 2; mi++)
        #pragma unroll
        for (int ni = 0; ni < 8; ni++)
            #pragma unroll
            for (int r = 0; r < 4; r++) acc[mi][ni][r] = 0.0f;

    auto issue = [&](int st, int k0) {
        bf16* as = Asm + st * 128 * ASTR;
        bf16* bs = Bsm + st * 32 * BSTR;
        #pragma unroll
        for (int i = 0; i < 2; i++) {
            int idx = tid + i * 256;
            int ar = idx >> 2, ach = idx & 3;
            cp16(&as[ar * ASTR + ach * 8],
                 &A[(size_t)(bm + ar) * DD + k0 + ach * 8]);
            int br = idx >> 4, bch = idx & 15;
            cp16(&bs[br * BSTR + bch * 8],
                 &B[(size_t)(k0 + br) * (3 * DD) + bn + bch * 8]);
        }
    };

    #pragma unroll
    for (int s = 0; s < 3; s++) { issue(s, s * 32); CP_COMMIT; }

    for (int kt = 0; kt < DD / 32; kt++) {
        CP_WAIT(2);
        __syncthreads();
        if (kt + 3 < DD / 32) issue((kt + 3) & 3, (kt + 3) * 32);
        CP_COMMIT;

        const bf16* as = Asm + (kt & 3) * 128 * ASTR;
        const bf16* bs = Bsm + (kt & 3) * 32 * BSTR;
        #pragma unroll
        for (int kk = 0; kk < 2; kk++) {
            unsigned af[2][4], bfg[8][2];
            #pragma unroll
            for (int mi = 0; mi < 2; mi++) {
                int row = wm + mi * 16 + (lane & 15);
                int col = kk * 16 + 8 * (lane >> 4);
                ldsm_x4(af[mi][0], af[mi][1], af[mi][2], af[mi][3],
                        &as[row * ASTR + col]);
            }
            #pragma unroll
            for (int nj = 0; nj < 4; nj++) {
                int row = kk * 16 + (lane & 7) + 8 * ((lane >> 3) & 1);
                int col = wn + nj * 16 + 8 * (lane >> 4);
                unsigned r0, r1, r2, r3;
                ldsm_x4t(r0, r1, r2, r3, &bs[row * BSTR + col]);
                bfg[nj * 2][0] = r0; bfg[nj * 2][1] = r1;
                bfg[nj * 2 + 1][0] = r2; bfg[nj * 2 + 1][1] = r3;
            }
            #pragma unroll
            for (int mi = 0; mi < 2; mi++)
                #pragma unroll
                for (int ni = 0; ni < 8; ni++)
                    mma_bf16(acc[mi][ni], af[mi], bfg[ni]);
        }
    }

    if (seg == 2) {
        // V: plain bf16 store
        #pragma unroll
        for (int mi = 0; mi < 2; mi++) {
            #pragma unroll
            for (int ni = 0; ni < 8; ni++) {
                int col = coln + wn + ni * 8 + 2 * tig;
                #pragma unroll
                for (int half = 0; half < 2; half++) {
                    int row = bm + wm + mi * 16 + gid + half * 8;
                    *(unsigned*)(Cv + (size_t)row * DD + col) =
                        packbf(acc[mi][ni][half * 2], acc[mi][ni][half * 2 + 1]);
                }
            }
        }
    } else {
        // Q/K: fused RoPE on fp32 accumulators, then bf16 store
        bf16* Cb = (seg == 0) ? Cq : Ck;
        #pragma unroll
        for (int mi = 0; mi < 2; mi++) {
            #pragma unroll
            for (int half = 0; half < 2; half++) {
                int row = bm + wm + mi * 16 + gid + half * 8;
                int n = row & (NN - 1);
                const float* rp = rope + (size_t)n * HD;
                #pragma unroll
                for (int ni = 0; ni < 4; ni++) {
                    int d0 = ni * 8 + 2 * tig;     // in-head index < 32
                    float lo0 = acc[mi][ni][half * 2 + 0];
                    float lo1 = acc[mi][ni][half * 2 + 1];
                    float hi0 = acc[mi][ni + 4][half * 2 + 0];
                    float hi1 = acc[mi][ni + 4][half * 2 + 1];
                    float c10, s10, c11, s11, c20, s20, c21, s21;
                    __sincosf(rp[d0],      &s10, &c10);
                    __sincosf(rp[d0 + 1],  &s11, &c11);
                    __sincosf(rp[d0 + 32], &s20, &c20);
                    __sincosf(rp[d0 + 33], &s21, &c21);
                    float q_lo0 = lo0 * c10 - hi0 * s10;
                    float q_lo1 = lo1 * c11 - hi1 * s11;
                    float q_hi0 = hi0 * c20 + lo0 * s20;
                    float q_hi1 = hi1 * c21 + lo1 * s21;
                    int gc = coln + wn + d0;
                    *(unsigned*)(Cb + (size_t)row * DD + gc)      = packbf(q_lo0, q_lo1);
                    *(unsigned*)(Cb + (size_t)row * DD + gc + 32) = packbf(q_hi0, q_hi1);
                }
            }
        }
    }
}

// ---------------------------------------------------------------------------
// Output GEMM: out = x + gate * (ao @ Wo).  64x32 warp tiles, fp32 epilogue.
// ---------------------------------------------------------------------------
__global__ __launch_bounds__(256, 2)
void tgemm_out(const bf16* __restrict__ A, const bf16* __restrict__ B,
               float* __restrict__ Cf, const float* __restrict__ X,
               const float* __restrict__ gate) {
    extern __shared__ bf16 smg[];
    bf16* Asm = smg;
    bf16* Bsm = smg + GSTAGES * 128 * ASTR;

    const int bm = blockIdx.y * 128;
    const int bn = blockIdx.x * 128;

    const int tid = threadIdx.x;
    const int warp = tid >> 5, lane = tid & 31;
    const int gid = lane >> 2, tig = lane & 3;
    const int wm = (warp >> 2) * 64;
    const int wn = (warp & 3) * 32;

    float acc[4][4][4];
    #pragma unroll
    for (int mi = 0; mi < 4; mi++)
        #pragma unroll
        for (int ni = 0; ni < 4; ni++)
            #pragma unroll
            for (int r = 0; r < 4; r++) acc[mi][ni][r] = 0.0f;

    auto issue = [&](int st, int k0) {
        bf16* as = Asm + st * 128 * ASTR;
        bf16* bs = Bsm + st * 32 * BSTR;
        #pragma unroll
        for (int i = 0; i < 2; i++) {
            int idx = tid + i * 256;
            int ar = idx >> 2, ach = idx & 3;
            cp16(&as[ar * ASTR + ach * 8],
                 &A[(size_t)(bm + ar) * DD + k0 + ach * 8]);
            int br = idx >> 4, bch = idx & 15;
            cp16(&bs[br * BSTR + bch * 8],
                 &B[(size_t)(k0 + br) * DD + bn + bch * 8]);
        }
    };

    #pragma unroll
    for (int s = 0; s < 3; s++) { issue(s, s * 32); CP_COMMIT; }

    for (int kt = 0; kt < DD / 32; kt++) {
        CP_WAIT(2);
        __syncthreads();
        if (kt + 3 < DD / 32) issue((kt + 3) & 3, (kt + 3) * 32);
        CP_COMMIT;

        const bf16* as = Asm + (kt & 3) * 128 * ASTR;
        const bf16* bs = Bsm + (kt & 3) * 32 * BSTR;
        #pragma unroll
        for (int kk = 0; kk < 2; kk++) {
            unsigned af[4][4], bfg[4][2];
            #pragma unroll
            for (int mi = 0; mi < 4; mi++) {
                int row = wm + mi * 16 + (lane & 15);
                int col = kk * 16 + 8 * (lane >> 4);
                ldsm_x4(af[mi][0], af[mi][1], af[mi][2], af[mi][3],
                        &as[row * ASTR + col]);
            }
            #pragma unroll
            for (int nj = 0; nj < 2; nj++) {
                int row = kk * 16 + (lane & 7) + 8 * ((lane >> 3) & 1);
                int col = wn + nj * 16 + 8 * (lane >> 4);
                unsigned r0, r1, r2, r3;
                ldsm_x4t(r0, r1, r2, r3, &bs[row * BSTR + col]);
                bfg[nj * 2][0] = r0; bfg[nj * 2][1] = r1;
                bfg[nj * 2 + 1][0] = r2; bfg[nj * 2 + 1][1] = r3;
            }
            #pragma unroll
            for (int mi = 0; mi < 4; mi++)
                #pragma unroll
                for (int ni = 0; ni < 4; ni++)
                    mma_bf16(acc[mi][ni], af[mi], bfg[ni]);
        }
    }

    #pragma unroll
    for (int mi = 0; mi < 4; mi++) {
        #pragma unroll
        for (int ni = 0; ni < 4; ni++) {
            int col = bn + wn + ni * 8 + 2 * tig;
            #pragma unroll
            for (int half = 0; half < 2; half++) {
                int row = bm + wm + mi * 16 + gid + half * 8;
                int bidx = row >> 11;
                float2 xv = *(const float2*)(X + (size_t)row * DD + col);
                float2 gv = *(const float2*)(gate + bidx * DD + col);
                float2 r;
                r.x = xv.x + gv.x * acc[mi][ni][half * 2 + 0];
                r.y = xv.y + gv.y * acc[mi][ni][half * 2 + 1];
                *(float2*)(Cf + (size_t)row * DD + col) = r;
            }
        }
    }
}

// ---------------------------------------------------------------------------
// Flash attention, bf16 mma. grid (N/128, H, B), 256 threads (8 warps).
// 128-row Q tile, 3-stage KV ring, P in registers, exp2 softmax with
// skip-rescale when the running max is unchanged.
// ---------------------------------------------------------------------------
#define QSTR 72
#define ATTN_SMEM ((128 * QSTR + 6 * 64 * QSTR) * 2)
#define SOFTMAX_SCALE 0.18033688f   // 0.125 * log2(e)

__global__ __launch_bounds__(256, 2)
void attn_kernel(const bf16* __restrict__ q, const bf16* __restrict__ k,
                 const bf16* __restrict__ v, bf16* __restrict__ o) {
    extern __shared__ bf16 sma[];
    bf16* Qs  = sma;
    bf16* KVs = sma + 128 * QSTR;

    const int qt = blockIdx.x, h = blockIdx.y, b = blockIdx.z;
    const int tid = threadIdx.x;
    const int warp = tid >> 5, lane = tid & 31;
    const int gid = lane >> 2, tig = lane & 3;
    const int hoff = h * HD;
    const size_t bbase = (size_t)b * NN * DD;

    auto issue_kv = [&](int kt, int st) {
        bf16* Ks = KVs + st * 2 * 64 * QSTR;
        bf16* Vs = Ks + 64 * QSTR;
        #pragma unroll
        for (int i = 0; i < 2; i++) {
            int idx = tid + i * 256;
            int r = idx >> 3, ch = idx & 7;
            size_t g = bbase + (size_t)(kt * 64 + r) * DD + hoff + ch * 8;
            cp16(&Ks[r * QSTR + ch * 8], &k[g]);
            cp16(&Vs[r * QSTR + ch * 8], &v[g]);
        }
    };

    #pragma unroll
    for (int i = 0; i < 4; i++) {
        int idx = tid + i * 256;
        int r = idx >> 3, ch = idx & 7;
        cp16(&Qs[r * QSTR + ch * 8],
             &q[bbase + (size_t)(qt * 128 + r) * DD + hoff + ch * 8]);
    }
    issue_kv(0, 0);
    CP_COMMIT;
    issue_kv(1, 1);
    CP_COMMIT;

    unsigned qa[4][4];
    float m_i[2] = {-1e30f, -1e30f};
    float l_i[2] = {0.0f, 0.0f};
    float O[8][4];
    #pragma unroll
    for (int ni = 0; ni < 8; ni++)
        #pragma unroll
        for (int r = 0; r < 4; r++) O[ni][r] = 0.0f;

    for (int kt = 0; kt < NN / 64; kt++) {
        CP_WAIT(1);
        __syncthreads();
        if (kt + 2 < NN / 64) issue_kv(kt + 2, (kt + 2) % 3);
        CP_COMMIT;

        if (kt == 0) {
            #pragma unroll
            for (int kk = 0; kk < 4; kk++) {
                int row = warp * 16 + (lane & 15);
                int col = kk * 16 + 8 * (lane >> 4);
                ldsm_x4(qa[kk][0], qa[kk][1], qa[kk][2], qa[kk][3],
                        &Qs[row * QSTR + col]);
            }
        }

        const bf16* ks = KVs + (kt % 3) * 2 * 64 * QSTR;
        const bf16* vs = ks + 64 * QSTR;

        float S[8][4];
        #pragma unroll
        for (int ni = 0; ni < 8; ni++)
            #pragma unroll
            for (int r = 0; r < 4; r++) S[ni][r] = 0.0f;
        #pragma unroll
        for (int kk = 0; kk < 4; kk++) {
            #pragma unroll
            for (int nj = 0; nj < 4; nj++) {
                int row = nj * 16 + (lane & 7) + 8 * (lane >> 4);
                int col = kk * 16 + 8 * ((lane >> 3) & 1);
                unsigned r0, r1, r2, r3;
                ldsm_x4(r0, r1, r2, r3, &ks[row * QSTR + col]);
                unsigned b0[2] = {r0, r1}, b1[2] = {r2, r3};
                mma_bf16(S[nj * 2],     qa[kk], b0);
                mma_bf16(S[nj * 2 + 1], qa[kk], b1);
            }
        }
        #pragma unroll
        for (int ni = 0; ni < 8; ni++)
            #pragma unroll
            for (int r = 0; r < 4; r++) S[ni][r] *= SOFTMAX_SCALE;

        // online softmax in exp2 domain; skip O-rescale when max unchanged
        #pragma unroll
        for (int half = 0; half < 2; half++) {
            float mx = -1e30f;
            #pragma unroll
            for (int ni = 0; ni < 8; ni++)
                mx = fmaxf(mx, fmaxf(S[ni][half * 2], S[ni][half * 2 + 1]));
            mx = fmaxf(mx, __shfl_xor_sync(0xffffffffu, mx, 1));
            mx = fmaxf(mx, __shfl_xor_sync(0xffffffffu, mx, 2));
            float fac = 1.0f;
            if (mx > m_i[half]) {
                fac = exp2f(m_i[half] - mx);
                m_i[half] = mx;
                #pragma unroll
                for (int ni = 0; ni < 8; ni++) {
                    O[ni][half * 2]     *= fac;
                    O[ni][half * 2 + 1] *= fac;
                }
            }
            float mnew = m_i[half];
            float rs = 0.0f;
            #pragma unroll
            for (int ni = 0; ni < 8; ni++) {
                float p0 = exp2f(S[ni][half * 2]     - mnew);
                float p1 = exp2f(S[ni][half * 2 + 1] - mnew);
                S[ni][half * 2]     = p0;
                S[ni][half * 2 + 1] = p1;
                rs += p0 + p1;
            }
            rs += __shfl_xor_sync(0xffffffffu, rs, 1);
            rs += __shfl_xor_sync(0xffffffffu, rs, 2);
            l_i[half] = l_i[half] * fac + rs;
        }

        unsigned pa[4][4];
        #pragma unroll
        for (int kk2 = 0; kk2 < 4; kk2++) {
            pa[kk2][0] = packbf(S[2 * kk2][0],     S[2 * kk2][1]);
            pa[kk2][1] = packbf(S[2 * kk2][2],     S[2 * kk2][3]);
            pa[kk2][2] = packbf(S[2 * kk2 + 1][0], S[2 * kk2 + 1][1]);
            pa[kk2][3] = packbf(S[2 * kk2 + 1][2], S[2 * kk2 + 1][3]);
        }

        #pragma unroll
        for (int kk2 = 0; kk2 < 4; kk2++) {
            #pragma unroll
            for (int nj = 0; nj < 4; nj++) {
                int row = kk2 * 16 + (lane & 7) + 8 * ((lane >> 3) & 1);
                int col = nj * 16 + 8 * (lane >> 4);
                unsigned r0, r1, r2, r3;
                ldsm_x4t(r0, r1, r2, r3, &vs[row * QSTR + col]);
                unsigned b0[2] = {r0, r1}, b1[2] = {r2, r3};
                mma_bf16(O[nj * 2],     pa[kk2], b0);
                mma_bf16(O[nj * 2 + 1], pa[kk2], b1);
            }
        }
    }

    float inv0 = 1.0f / l_i[0], inv1 = 1.0f / l_i[1];
    #pragma unroll
    for (int ni = 0; ni < 8; ni++) {
        int col = hoff + ni * 8 + 2 * tig;
        int row0 = qt * 128 + warp * 16 + gid;
        *(unsigned*)(o + bbase + (size_t)row0 * DD + col) =
            packbf(O[ni][0] * inv0, O[ni][1] * inv0);
        *(unsigned*)(o + bbase + (size_t)(row0 + 8) * DD + col) =
            packbf(O[ni][2] * inv1, O[ni][3] * inv1);
    }
}

// ---------------------------------------------------------------------------
// Launcher
// ---------------------------------------------------------------------------
extern "C" void kernel_launch(void* const* d_in, const int* in_sizes, int n_in,
                              void* d_out, int out_size) {
    const float* x     = (const float*)d_in[0];
    const float* emb   = (const float*)d_in[1];
    const float* gate  = (const float*)d_in[2];
    // d_in[3] = crossattn_emb: unused by the reference
    const float* rope  = (const float*)d_in[4];
    const float* Wq1   = (const float*)d_in[5];
    const float* Wq2   = (const float*)d_in[6];
    const float* Wk1   = (const float*)d_in[7];
    const float* Wk2   = (const float*)d_in[8];
    const float* Wv    = (const float*)d_in[9];
    const float* Wo    = (const float*)d_in[10];
    const float* Wada1 = (const float*)d_in[11];
    const float* Wada2 = (const float*)d_in[12];
    const float* bada2 = (const float*)d_in[13];
    float* out = (float*)d_out;

    bf16 *xn_p, *tmp_p, *q_p, *k_p, *v_p, *ao_p, *w1_p, *wo_p;
    float *h_p, *ada_p;
    cudaGetSymbolAddress((void**)&xn_p,  g_xn);
    cudaGetSymbolAddress((void**)&tmp_p, g_tmp);
    cudaGetSymbolAddress((void**)&q_p,   g_q);
    cudaGetSymbolAddress((void**)&k_p,   g_k);
    cudaGetSymbolAddress((void**)&v_p,   g_v);
    cudaGetSymbolAddress((void**)&ao_p,  g_ao);
    cudaGetSymbolAddress((void**)&h_p,   g_h);
    cudaGetSymbolAddress((void**)&ada_p, g_ada);
    cudaGetSymbolAddress((void**)&w1_p,  g_w1);
    cudaGetSymbolAddress((void**)&wo_p,  g_wo);

    cudaFuncSetAttribute(wgemm,     cudaFuncAttributeMaxDynamicSharedMemorySize, GEMM_SMEM);
    cudaFuncSetAttribute(qkv_rope,  cudaFuncAttributeMaxDynamicSharedMemorySize, GEMM_SMEM);
    cudaFuncSetAttribute(tgemm_out, cudaFuncAttributeMaxDynamicSharedMemorySize, GEMM_SMEM);
    cudaFuncSetAttribute(attn_kernel, cudaFuncAttributeMaxDynamicSharedMemorySize, ATTN_SMEM);

    // pack weights -> bf16 staging (+ Wv, Wo into final layouts)
    pack_all<<<dim3(1024, 6), 256>>>(Wq1, Wq2, Wk1, Wk2, Wv, Wo,
                                     tmp_p, w1_p, wo_p);

    // combine stacked projections: w1 seg0 = Wq1@Wq2, seg1 = Wk1@Wk2
    wgemm<<<dim3(16, 8), 256, GEMM_SMEM>>>(tmp_p, w1_p);

    // adaLN modulation
    ada_fc1<<<dim3(4, 2), 256>>>(emb, Wada1, h_p);
    ada_fc2<<<dim3(8, 2), 256>>>(h_p, Wada2, bada2, ada_p);

    // LayerNorm + scale/shift -> bf16
    ln_mod<<<MM, 256>>>(x, ada_p, xn_p);

    // Fused QKV projection + RoPE: [q|k|v] = xn @ [Wq12|Wk12|Wv]
    qkv_rope<<<dim3(24, 32), 256, GEMM_SMEM>>>(xn_p, w1_p, rope,
                                               q_p, k_p, v_p);

    // Attention (128-row Q tiles, 3-stage KV pipeline, 2 CTAs/SM)
    attn_kernel<<<dim3(NN / 128, HH, BB), 256, ATTN_SMEM>>>(q_p, k_p, v_p, ao_p);

    // Output GEMM: out = x + gate * (ao @ Wo)
    tgemm_out<<<dim3(8, 32), 256, GEMM_SMEM>>>(ao_p, wo_p, out, x, gate);
}